// round 1
// baseline (speedup 1.0000x reference)
#include <cuda_runtime.h>
#include <math.h>

#define Nn 32768
#define Dd 256
#define Ee 8
#define Hh 1024
#define MT 32
#define HC 64

// ---------------- device scratch (static, no allocation) ----------------
__device__ int   g_counts[Ee];
__device__ int   g_cursor[Ee];
__device__ int   g_off[Ee + 1];
__device__ int   g_tileoff[Ee + 1];
__device__ int   g_tok_e[Nn];      // packed e1 | e2<<8
__device__ float g_tok_p1[Nn];
__device__ float g_tok_p2[Nn];
__device__ int   g_gtok[Nn * 2];   // gathered token ids per expert segment
__device__ float g_gp[Nn * 2];     // gathered combine weights

// ---------------- kernel 0: zero out + counters ----------------
__global__ void zero_kernel(float4* out4) {
    int i = blockIdx.x * blockDim.x + threadIdx.x;
    if (i < (Nn * Dd / 4)) out4[i] = make_float4(0.f, 0.f, 0.f, 0.f);
    if (blockIdx.x == 0 && threadIdx.x < Ee) {
        g_counts[threadIdx.x] = 0;
        g_cursor[threadIdx.x] = 0;
    }
}

// ---------------- kernel 1: router (warp per token, fp32) ----------------
__global__ void router_kernel(const float* __restrict__ x,
                              const float* __restrict__ grad,
                              const float* __restrict__ Wr,
                              const float* __restrict__ br,
                              float* __restrict__ probs_out) {
    __shared__ float WrT[Ee][Dd + 1];   // transposed: conflict-free reads
    int tid = threadIdx.x;
    for (int i = tid; i < (Dd + 1) * Ee; i += blockDim.x) {
        int d = i >> 3, e = i & 7;
        WrT[e][d] = Wr[i];
    }
    __syncthreads();

    int wid = tid >> 5, lane = tid & 31;
    int n = blockIdx.x * 8 + wid;
    const float* xr = x + (size_t)n * Dd;

    float a[8];
#pragma unroll
    for (int e = 0; e < 8; e++) a[e] = 0.f;
#pragma unroll
    for (int j = 0; j < 8; j++) {
        float xv = xr[lane + 32 * j];
#pragma unroll
        for (int e = 0; e < 8; e++) a[e] += xv * WrT[e][lane + 32 * j];
    }
#pragma unroll
    for (int off = 16; off > 0; off >>= 1) {
#pragma unroll
        for (int e = 0; e < 8; e++) a[e] += __shfl_xor_sync(0xffffffffu, a[e], off);
    }

    if (lane == 0) {
        float g = grad[n];
        float p[8];
        float m = -1e30f;
#pragma unroll
        for (int e = 0; e < 8; e++) {
            p[e] = a[e] + g * WrT[e][Dd] + br[e];
            m = fmaxf(m, p[e]);
        }
        float s = 0.f;
#pragma unroll
        for (int e = 0; e < 8; e++) { p[e] = expf(p[e] - m); s += p[e]; }
        float inv = 1.f / s;
#pragma unroll
        for (int e = 0; e < 8; e++) {
            p[e] *= inv;
            probs_out[(size_t)n * 8 + e] = p[e];
        }
        // top-2, lowest-index tie break (matches jax.lax.top_k)
        int e1 = 0;
#pragma unroll
        for (int e = 1; e < 8; e++) if (p[e] > p[e1]) e1 = e;
        int e2 = (e1 == 0) ? 1 : 0;
#pragma unroll
        for (int e = 0; e < 8; e++) if (e != e1 && p[e] > p[e2]) e2 = e;

        g_tok_e[n]  = e1 | (e2 << 8);
        g_tok_p1[n] = p[e1];
        g_tok_p2[n] = p[e2];
        atomicAdd(&g_counts[e1], 1);
        atomicAdd(&g_counts[e2], 1);
    }
}

// ---------------- kernel 2: tiny scan ----------------
__global__ void scan_kernel() {
    if (threadIdx.x == 0) {
        int o = 0, t = 0;
#pragma unroll
        for (int e = 0; e < Ee; e++) {
            g_off[e] = o;
            g_tileoff[e] = t;
            o += g_counts[e];
            t += (g_counts[e] + MT - 1) / MT;
        }
        g_off[Ee] = o;
        g_tileoff[Ee] = t;
    }
}

// ---------------- kernel 3: scatter tokens into expert lists ----------------
__global__ void scatter_kernel() {
    int n = blockIdx.x * blockDim.x + threadIdx.x;
    if (n >= Nn) return;
    int pk = g_tok_e[n];
    int e1 = pk & 255, e2 = (pk >> 8) & 255;
    int i1 = g_off[e1] + atomicAdd(&g_cursor[e1], 1);
    g_gtok[i1] = n; g_gp[i1] = g_tok_p1[n];
    int i2 = g_off[e2] + atomicAdd(&g_cursor[e2], 1);
    g_gtok[i2] = n; g_gp[i2] = g_tok_p2[n];
}

// ---------------- kernel 4: fused expert FFN ----------------
__device__ __forceinline__ float gelu_exact(float v) {
    return 0.5f * v * (1.f + erff(v * 0.70710678118654752f));
}

__global__ __launch_bounds__(256, 2)
void expert_kernel(const float* __restrict__ x,
                   const float* __restrict__ W1, const float* __restrict__ b1,
                   const float* __restrict__ W2, const float* __restrict__ b2,
                   float* __restrict__ out) {
    extern __shared__ float smem[];
    float* Xs = smem;                    // [MT][Dd]            32 KB
    float* Wc = Xs + MT * Dd;            // W1 chunk [Dd][HC] / W2 chunk [HC][Dd]  64 KB
    float* Hs = Wc + HC * Dd;            // [MT][HC]             8 KB
    __shared__ int   s_tok[MT];
    __shared__ float s_p[MT];

    int b = blockIdx.x;
    if (b >= g_tileoff[Ee]) return;
    int e = 0;
#pragma unroll
    for (int i = 1; i < Ee; i++) if (b >= g_tileoff[i]) e = i;
    int tile   = b - g_tileoff[e];
    int row0   = g_off[e] + tile * MT;
    int nrows  = min(MT, g_off[e + 1] - row0);

    int tid = threadIdx.x;
    if (tid < MT) {
        if (tid < nrows) { s_tok[tid] = g_gtok[row0 + tid]; s_p[tid] = g_gp[row0 + tid]; }
        else             { s_tok[tid] = 0;                  s_p[tid] = 0.f; }
    }
    __syncthreads();
    for (int i = tid; i < MT * Dd; i += 256) {
        int r = i >> 8;
        Xs[i] = (r < nrows) ? x[(size_t)s_tok[r] * Dd + (i & (Dd - 1))] : 0.f;
    }

    const float* W1e = W1 + (size_t)e * Dd * Hh;
    const float* W2e = W2 + (size_t)e * Hh * Dd;
    const float* b1e = b1 + e * Hh;

    float acc[4][8];
#pragma unroll
    for (int i = 0; i < 4; i++)
#pragma unroll
        for (int j = 0; j < 8; j++) acc[i][j] = 0.f;

    int rg = tid >> 4, cg = tid & 15;   // phase1: rows {2rg,2rg+1}, cols cg*4..+3
    int ty = tid >> 5, tx = tid & 31;   // phase2: rows ty*4+i, cols tx*4 and tx*4+128

    for (int hcs = 0; hcs < Hh; hcs += HC) {
        __syncthreads();  // Wc + Hs free (previous phase2 done)
        // load W1 chunk: Wc[d*HC + j] = W1e[d*Hh + hcs + j]
        for (int i = tid; i < Dd * HC; i += 256) {
            int d = i >> 6, j = i & 63;
            Wc[i] = W1e[(size_t)d * Hh + hcs + j];
        }
        __syncthreads();
        // ---- phase 1: Hs = gelu(Xs @ W1chunk + b1) ----
        {
            int r0 = rg * 2, c0 = cg * 4;
            float4 h0 = make_float4(0, 0, 0, 0), h1 = make_float4(0, 0, 0, 0);
            const float4* X0 = (const float4*)(Xs + r0 * Dd);
            const float4* X1 = (const float4*)(Xs + (r0 + 1) * Dd);
#pragma unroll 8
            for (int k4 = 0; k4 < Dd / 4; k4++) {
                float4 a0 = X0[k4];
                float4 a1 = X1[k4];
                const float* wb = Wc + (k4 * 4) * HC + c0;
                float4 w0 = *(const float4*)(wb);
                float4 w1 = *(const float4*)(wb + HC);
                float4 w2 = *(const float4*)(wb + 2 * HC);
                float4 w3 = *(const float4*)(wb + 3 * HC);
                h0.x += a0.x * w0.x + a0.y * w1.x + a0.z * w2.x + a0.w * w3.x;
                h0.y += a0.x * w0.y + a0.y * w1.y + a0.z * w2.y + a0.w * w3.y;
                h0.z += a0.x * w0.z + a0.y * w1.z + a0.z * w2.z + a0.w * w3.z;
                h0.w += a0.x * w0.w + a0.y * w1.w + a0.z * w2.w + a0.w * w3.w;
                h1.x += a1.x * w0.x + a1.y * w1.x + a1.z * w2.x + a1.w * w3.x;
                h1.y += a1.x * w0.y + a1.y * w1.y + a1.z * w2.y + a1.w * w3.y;
                h1.z += a1.x * w0.z + a1.y * w1.z + a1.z * w2.z + a1.w * w3.z;
                h1.w += a1.x * w0.w + a1.y * w1.w + a1.z * w2.w + a1.w * w3.w;
            }
            float4 bv = *(const float4*)(b1e + hcs + c0);
            h0.x = gelu_exact(h0.x + bv.x); h0.y = gelu_exact(h0.y + bv.y);
            h0.z = gelu_exact(h0.z + bv.z); h0.w = gelu_exact(h0.w + bv.w);
            h1.x = gelu_exact(h1.x + bv.x); h1.y = gelu_exact(h1.y + bv.y);
            h1.z = gelu_exact(h1.z + bv.z); h1.w = gelu_exact(h1.w + bv.w);
            *(float4*)(Hs + r0 * HC + c0)       = h0;
            *(float4*)(Hs + (r0 + 1) * HC + c0) = h1;
        }
        __syncthreads();  // Hs written, Wc reads done
        // load W2 chunk (contiguous 64x256 slab)
        {
            const float4* src = (const float4*)(W2e + (size_t)hcs * Dd);
            float4* dst = (float4*)Wc;
            for (int i = tid; i < HC * Dd / 4; i += 256) dst[i] = src[i];
        }
        __syncthreads();
        // ---- phase 2: acc += Hs @ W2chunk ----
        {
            const float4* H0 = (const float4*)(Hs + (ty * 4 + 0) * HC);
            const float4* H1 = (const float4*)(Hs + (ty * 4 + 1) * HC);
            const float4* H2 = (const float4*)(Hs + (ty * 4 + 2) * HC);
            const float4* H3 = (const float4*)(Hs + (ty * 4 + 3) * HC);
            int cA = tx * 4, cB = tx * 4 + 128;
#pragma unroll 4
            for (int k4 = 0; k4 < HC / 4; k4++) {
                float4 h4[4];
                h4[0] = H0[k4]; h4[1] = H1[k4]; h4[2] = H2[k4]; h4[3] = H3[k4];
#pragma unroll
                for (int kk = 0; kk < 4; kk++) {
                    const float* wrow = Wc + (k4 * 4 + kk) * Dd;
                    float4 wA = *(const float4*)(wrow + cA);
                    float4 wB = *(const float4*)(wrow + cB);
#pragma unroll
                    for (int i = 0; i < 4; i++) {
                        float hv = ((const float*)&h4[i])[kk];
                        acc[i][0] += hv * wA.x; acc[i][1] += hv * wA.y;
                        acc[i][2] += hv * wA.z; acc[i][3] += hv * wA.w;
                        acc[i][4] += hv * wB.x; acc[i][5] += hv * wB.y;
                        acc[i][6] += hv * wB.z; acc[i][7] += hv * wB.w;
                    }
                }
            }
        }
    }

    // ---- writeback: out[tok] += p * (acc + b2) ----
    const float* b2e = b2 + e * Dd;
    int cA = tx * 4, cB = tx * 4 + 128;
    float4 bA = *(const float4*)(b2e + cA);
    float4 bB = *(const float4*)(b2e + cB);
#pragma unroll
    for (int i = 0; i < 4; i++) {
        int r = ty * 4 + i;
        if (r < nrows) {
            float p = s_p[r];
            float* orow = out + (size_t)s_tok[r] * Dd;
            atomicAdd(orow + cA + 0, (acc[i][0] + bA.x) * p);
            atomicAdd(orow + cA + 1, (acc[i][1] + bA.y) * p);
            atomicAdd(orow + cA + 2, (acc[i][2] + bA.z) * p);
            atomicAdd(orow + cA + 3, (acc[i][3] + bA.w) * p);
            atomicAdd(orow + cB + 0, (acc[i][4] + bB.x) * p);
            atomicAdd(orow + cB + 1, (acc[i][5] + bB.y) * p);
            atomicAdd(orow + cB + 2, (acc[i][6] + bB.z) * p);
            atomicAdd(orow + cB + 3, (acc[i][7] + bB.w) * p);
        }
    }
}

// ---------------- launcher ----------------
extern "C" void kernel_launch(void* const* d_in, const int* in_sizes, int n_in,
                              void* d_out, int out_size) {
    const float* x    = (const float*)d_in[0];
    const float* grad = (const float*)d_in[1];
    const float* Wr   = (const float*)d_in[2];
    const float* br   = (const float*)d_in[3];
    const float* W1   = (const float*)d_in[4];
    const float* b1   = (const float*)d_in[5];
    const float* W2   = (const float*)d_in[6];
    const float* b2   = (const float*)d_in[7];
    float* out   = (float*)d_out;
    float* probs = out + (size_t)Nn * Dd;   // outputs: [out (N*D) | probs (N*E)]

    const int smem_bytes = (MT * Dd + HC * Dd + MT * HC) * sizeof(float);  // 106496
    cudaFuncSetAttribute(expert_kernel,
                         cudaFuncAttributeMaxDynamicSharedMemorySize, smem_bytes);

    zero_kernel<<<(Nn * Dd / 4 + 255) / 256, 256>>>((float4*)out);
    router_kernel<<<Nn / 8, 256>>>(x, grad, Wr, br, probs);
    scan_kernel<<<1, 32>>>();
    scatter_kernel<<<Nn / 256, 256>>>();
    // max tiles = N*K/MT + E = 2048 + 8
    expert_kernel<<<Nn * 2 / MT + Ee, 256, smem_bytes>>>(x, W1, b1, W2, b2, out);
}

// round 2
// speedup vs baseline: 2.5177x; 2.5177x over previous
#include <cuda_runtime.h>
#include <cuda_bf16.h>
#include <math.h>

#define Nn 32768
#define Dd 256
#define Ee 8
#define Hh 1024
#define MT 128          // token tile (M)
#define BK 32           // k slab
#define TILES_MAX (Nn * 2 / MT + Ee)   // 520

// ---------------- device scratch (static, no allocation) ----------------
__device__ int   g_counts[Ee];
__device__ int   g_cursor[Ee];
__device__ int   g_off[Ee + 1];
__device__ int   g_tileoff[Ee + 1];
__device__ int   g_tok_e[Nn];
__device__ float g_tok_p1[Nn];
__device__ float g_tok_p2[Nn];
__device__ int   g_gtok[Nn * 2];
__device__ float g_gp[Nn * 2];
__device__ float g_H[67108864];   // [N*K=65536][1024] fp32 hidden scratch (268 MB)

// ---------------- kernel 0: zero out + counters ----------------
__global__ void zero_kernel(float4* out4) {
    int i = blockIdx.x * blockDim.x + threadIdx.x;
    if (i < (Nn * Dd / 4)) out4[i] = make_float4(0.f, 0.f, 0.f, 0.f);
    if (blockIdx.x == 0 && threadIdx.x < Ee) {
        g_counts[threadIdx.x] = 0;
        g_cursor[threadIdx.x] = 0;
    }
}

// ---------------- kernel 1: router (warp per token, fp32) ----------------
__global__ void router_kernel(const float* __restrict__ x,
                              const float* __restrict__ grad,
                              const float* __restrict__ Wr,
                              const float* __restrict__ br,
                              float* __restrict__ probs_out) {
    __shared__ float WrT[Ee][Dd + 1];
    int tid = threadIdx.x;
    for (int i = tid; i < (Dd + 1) * Ee; i += blockDim.x) {
        int d = i >> 3, e = i & 7;
        WrT[e][d] = Wr[i];
    }
    __syncthreads();

    int wid = tid >> 5, lane = tid & 31;
    int n = blockIdx.x * 8 + wid;
    const float* xr = x + (size_t)n * Dd;

    float a[8];
#pragma unroll
    for (int e = 0; e < 8; e++) a[e] = 0.f;
#pragma unroll
    for (int j = 0; j < 8; j++) {
        float xv = xr[lane + 32 * j];
#pragma unroll
        for (int e = 0; e < 8; e++) a[e] += xv * WrT[e][lane + 32 * j];
    }
#pragma unroll
    for (int off = 16; off > 0; off >>= 1) {
#pragma unroll
        for (int e = 0; e < 8; e++) a[e] += __shfl_xor_sync(0xffffffffu, a[e], off);
    }

    if (lane == 0) {
        float g = grad[n];
        float p[8];
        float m = -1e30f;
#pragma unroll
        for (int e = 0; e < 8; e++) {
            p[e] = a[e] + g * WrT[e][Dd] + br[e];
            m = fmaxf(m, p[e]);
        }
        float s = 0.f;
#pragma unroll
        for (int e = 0; e < 8; e++) { p[e] = expf(p[e] - m); s += p[e]; }
        float inv = 1.f / s;
#pragma unroll
        for (int e = 0; e < 8; e++) {
            p[e] *= inv;
            probs_out[(size_t)n * 8 + e] = p[e];
        }
        int e1 = 0;
#pragma unroll
        for (int e = 1; e < 8; e++) if (p[e] > p[e1]) e1 = e;
        int e2 = (e1 == 0) ? 1 : 0;
#pragma unroll
        for (int e = 0; e < 8; e++) if (e != e1 && p[e] > p[e2]) e2 = e;

        g_tok_e[n]  = e1 | (e2 << 8);
        g_tok_p1[n] = p[e1];
        g_tok_p2[n] = p[e2];
        atomicAdd(&g_counts[e1], 1);
        atomicAdd(&g_counts[e2], 1);
    }
}

// ---------------- kernel 2: tiny scan ----------------
__global__ void scan_kernel() {
    if (threadIdx.x == 0) {
        int o = 0, t = 0;
#pragma unroll
        for (int e = 0; e < Ee; e++) {
            g_off[e] = o;
            g_tileoff[e] = t;
            o += g_counts[e];
            t += (g_counts[e] + MT - 1) / MT;
        }
        g_off[Ee] = o;
        g_tileoff[Ee] = t;
    }
}

// ---------------- kernel 3: scatter tokens into expert lists ----------------
__global__ void scatter_kernel() {
    int n = blockIdx.x * blockDim.x + threadIdx.x;
    if (n >= Nn) return;
    int pk = g_tok_e[n];
    int e1 = pk & 255, e2 = (pk >> 8) & 255;
    int i1 = g_off[e1] + atomicAdd(&g_cursor[e1], 1);
    g_gtok[i1] = n; g_gp[i1] = g_tok_p1[n];
    int i2 = g_off[e2] + atomicAdd(&g_cursor[e2], 1);
    g_gtok[i2] = n; g_gp[i2] = g_tok_p2[n];
}

// ---------------- MMA helpers ----------------
__device__ __forceinline__ unsigned smem_u32(const void* p) {
    return (unsigned)__cvta_generic_to_shared(p);
}
__device__ __forceinline__ void ldm4(unsigned addr, unsigned& r0, unsigned& r1,
                                     unsigned& r2, unsigned& r3) {
    asm volatile("ldmatrix.sync.aligned.m8n8.x4.shared.b16 {%0,%1,%2,%3},[%4];"
                 : "=r"(r0), "=r"(r1), "=r"(r2), "=r"(r3) : "r"(addr));
}
__device__ __forceinline__ void ldm4t(unsigned addr, unsigned& r0, unsigned& r1,
                                      unsigned& r2, unsigned& r3) {
    asm volatile("ldmatrix.sync.aligned.m8n8.x4.trans.shared.b16 {%0,%1,%2,%3},[%4];"
                 : "=r"(r0), "=r"(r1), "=r"(r2), "=r"(r3) : "r"(addr));
}
__device__ __forceinline__ void mma16816(float* c, unsigned a0, unsigned a1,
                                         unsigned a2, unsigned a3,
                                         unsigned b0, unsigned b1) {
    asm volatile(
        "mma.sync.aligned.m16n8k16.row.col.f32.bf16.bf16.f32 "
        "{%0,%1,%2,%3},{%4,%5,%6,%7},{%8,%9},{%0,%1,%2,%3};"
        : "+f"(c[0]), "+f"(c[1]), "+f"(c[2]), "+f"(c[3])
        : "r"(a0), "r"(a1), "r"(a2), "r"(a3), "r"(b0), "r"(b1));
}
// split (a,b) into bf16 hi pair + bf16 lo pair (packed b16x2)
__device__ __forceinline__ void hilo2(float a, float b, unsigned& hi, unsigned& lo) {
    __nv_bfloat16 ha = __float2bfloat16_rn(a), hb = __float2bfloat16_rn(b);
    float ra = a - __bfloat162float(ha);
    float rb = b - __bfloat162float(hb);
    __nv_bfloat16 la = __float2bfloat16_rn(ra), lb = __float2bfloat16_rn(rb);
    hi = (unsigned)__bfloat16_as_ushort(ha) | ((unsigned)__bfloat16_as_ushort(hb) << 16);
    lo = (unsigned)__bfloat16_as_ushort(la) | ((unsigned)__bfloat16_as_ushort(lb) << 16);
}
__device__ __forceinline__ float gelu_exact(float v) {
    return 0.5f * v * (1.f + erff(v * 0.70710678118654752f));
}

// ---------------- fused FFN passes on tensor cores ----------------
// PASS 1: g_H[slot,1024] = gelu(X[gathered]@W1[e] + b1)
// PASS 2: out[tok,256]  += p * (g_H[slot]@W2[e] + b2)
// 3x-bf16 compensated: acc = ah*bh + ah*bl + al*bh
template <int PASS>
__global__ void __launch_bounds__(256, 1)
ffn_mma_kernel(const float* __restrict__ Asrc, const float* __restrict__ W,
               const float* __restrict__ bias, float* __restrict__ dst) {
    constexpr int KD = (PASS == 1) ? Dd : Hh;
    constexpr int ND = (PASS == 1) ? Hh : Dd;
    constexpr int KS = KD / BK;

    __shared__ unsigned short Ah[MT][40], Al[MT][40];       // stride 40: ldmatrix conflict-free
    __shared__ unsigned short Bh[BK][136], Bl[BK][136];     // stride 136: conflict-free
    __shared__ int   s_tok[MT];
    __shared__ float s_p[MT];

    int b = blockIdx.x;
    if (b >= g_tileoff[Ee]) return;
    int e = 0;
#pragma unroll
    for (int i = 1; i < Ee; i++) if (b >= g_tileoff[i]) e = i;
    int tile  = b - g_tileoff[e];
    int row0  = g_off[e] + tile * MT;
    int nrows = min(MT, g_off[e + 1] - row0);
    int ncs   = blockIdx.y * 128;

    int tid = threadIdx.x;
    if (tid < MT) {
        if (tid < nrows) { s_tok[tid] = g_gtok[row0 + tid]; s_p[tid] = g_gp[row0 + tid]; }
        else             { s_tok[tid] = 0;                  s_p[tid] = 0.f; }
    }
    __syncthreads();

    // staging maps
    int ar  = tid >> 3, ac4 = (tid & 7) * 4;    // A rows ar+32i, 4 cols
    int br_ = tid >> 5, bc4 = (tid & 31) * 4;   // B rows br_+8i, 4 cols

    const float* We = W + (size_t)e * KD * ND;
    const float* aptr[4];
    bool avalid[4];
#pragma unroll
    for (int i = 0; i < 4; i++) {
        int r = ar + 32 * i;
        if (PASS == 1) {
            aptr[i] = Asrc + (size_t)s_tok[r] * Dd + ac4;
            avalid[i] = true;
        } else {
            avalid[i] = (r < nrows);
            aptr[i] = Asrc + (size_t)(row0 + r) * Hh + ac4;
        }
    }
    const float* bptr = We + (size_t)br_ * ND + ncs + bc4;

    int wid = tid >> 5, lane = tid & 31;
    int wm = wid >> 2, wn = wid & 3;
    int m0 = wm * 64, n0w = wn * 32;
    int lr = lane & 15, lc = (lane >> 4) << 3;

    float acc[4][4][4];
#pragma unroll
    for (int mi = 0; mi < 4; mi++)
#pragma unroll
        for (int ni = 0; ni < 4; ni++)
#pragma unroll
            for (int j = 0; j < 4; j++) acc[mi][ni][j] = 0.f;

    float4 pa[4], pb[4];
    // prologue: load k-slab 0
#pragma unroll
    for (int i = 0; i < 4; i++)
        pa[i] = avalid[i] ? *(const float4*)(aptr[i]) : make_float4(0, 0, 0, 0);
#pragma unroll
    for (int i = 0; i < 4; i++)
        pb[i] = *(const float4*)(bptr + (size_t)(8 * i) * ND);

    for (int ks = 0; ks < KS; ks++) {
        __syncthreads();   // previous compute done; smem free
        // ---- convert + store current slab ----
#pragma unroll
        for (int i = 0; i < 4; i++) {
            int r = ar + 32 * i;
            unsigned h0, l0, h1, l1;
            hilo2(pa[i].x, pa[i].y, h0, l0);
            hilo2(pa[i].z, pa[i].w, h1, l1);
            *(uint2*)&Ah[r][ac4] = make_uint2(h0, h1);
            *(uint2*)&Al[r][ac4] = make_uint2(l0, l1);
        }
#pragma unroll
        for (int i = 0; i < 4; i++) {
            int r = br_ + 8 * i;
            unsigned h0, l0, h1, l1;
            hilo2(pb[i].x, pb[i].y, h0, l0);
            hilo2(pb[i].z, pb[i].w, h1, l1);
            *(uint2*)&Bh[r][bc4] = make_uint2(h0, h1);
            *(uint2*)&Bl[r][bc4] = make_uint2(l0, l1);
        }
        __syncthreads();   // staging visible
        // ---- prefetch next slab (overlaps MMA below) ----
        if (ks + 1 < KS) {
            int ko = (ks + 1) * BK;
#pragma unroll
            for (int i = 0; i < 4; i++)
                pa[i] = avalid[i] ? *(const float4*)(aptr[i] + ko) : make_float4(0, 0, 0, 0);
#pragma unroll
            for (int i = 0; i < 4; i++)
                pb[i] = *(const float4*)(bptr + (size_t)(ko + 8 * i) * ND);
        }
        // ---- MMA on current slab (2 x k16) ----
#pragma unroll
        for (int k16 = 0; k16 < 2; k16++) {
            unsigned ah[4][4], al_[4][4], bh[4][2], bl[4][2];
#pragma unroll
            for (int mi = 0; mi < 4; mi++) {
                unsigned addr = smem_u32(&Ah[m0 + mi * 16 + lr][k16 * 16 + lc]);
                ldm4(addr, ah[mi][0], ah[mi][1], ah[mi][2], ah[mi][3]);
                addr = smem_u32(&Al[m0 + mi * 16 + lr][k16 * 16 + lc]);
                ldm4(addr, al_[mi][0], al_[mi][1], al_[mi][2], al_[mi][3]);
            }
#pragma unroll
            for (int nj = 0; nj < 2; nj++) {
                unsigned addr = smem_u32(&Bh[k16 * 16 + lr][n0w + nj * 16 + lc]);
                ldm4t(addr, bh[2 * nj][0], bh[2 * nj][1], bh[2 * nj + 1][0], bh[2 * nj + 1][1]);
                addr = smem_u32(&Bl[k16 * 16 + lr][n0w + nj * 16 + lc]);
                ldm4t(addr, bl[2 * nj][0], bl[2 * nj][1], bl[2 * nj + 1][0], bl[2 * nj + 1][1]);
            }
#pragma unroll
            for (int mi = 0; mi < 4; mi++)
#pragma unroll
                for (int ni = 0; ni < 4; ni++) {
                    mma16816(acc[mi][ni], ah[mi][0], ah[mi][1], ah[mi][2], ah[mi][3],
                             bh[ni][0], bh[ni][1]);
                    mma16816(acc[mi][ni], ah[mi][0], ah[mi][1], ah[mi][2], ah[mi][3],
                             bl[ni][0], bl[ni][1]);
                    mma16816(acc[mi][ni], al_[mi][0], al_[mi][1], al_[mi][2], al_[mi][3],
                             bh[ni][0], bh[ni][1]);
                }
        }
    }

    // ---- epilogue ----
    int gr = lane >> 2, gc = (lane & 3) * 2;
    const float* be = bias + (size_t)e * ND;
#pragma unroll
    for (int mi = 0; mi < 4; mi++) {
        int r1 = m0 + mi * 16 + gr;
        int r2 = r1 + 8;
#pragma unroll
        for (int ni = 0; ni < 4; ni++) {
            int col = ncs + n0w + ni * 8 + gc;
            float bv0 = be[col], bv1 = be[col + 1];
            if (PASS == 1) {
                if (r1 < nrows) {
                    float2 v = make_float2(gelu_exact(acc[mi][ni][0] + bv0),
                                           gelu_exact(acc[mi][ni][1] + bv1));
                    *(float2*)(dst + (size_t)(row0 + r1) * Hh + col) = v;
                }
                if (r2 < nrows) {
                    float2 v = make_float2(gelu_exact(acc[mi][ni][2] + bv0),
                                           gelu_exact(acc[mi][ni][3] + bv1));
                    *(float2*)(dst + (size_t)(row0 + r2) * Hh + col) = v;
                }
            } else {
                if (r1 < nrows) {
                    float p = s_p[r1];
                    float* orow = dst + (size_t)s_tok[r1] * Dd;
                    atomicAdd(orow + col,     (acc[mi][ni][0] + bv0) * p);
                    atomicAdd(orow + col + 1, (acc[mi][ni][1] + bv1) * p);
                }
                if (r2 < nrows) {
                    float p = s_p[r2];
                    float* orow = dst + (size_t)s_tok[r2] * Dd;
                    atomicAdd(orow + col,     (acc[mi][ni][2] + bv0) * p);
                    atomicAdd(orow + col + 1, (acc[mi][ni][3] + bv1) * p);
                }
            }
        }
    }
}

// ---------------- launcher ----------------
extern "C" void kernel_launch(void* const* d_in, const int* in_sizes, int n_in,
                              void* d_out, int out_size) {
    const float* x    = (const float*)d_in[0];
    const float* grad = (const float*)d_in[1];
    const float* Wr   = (const float*)d_in[2];
    const float* br   = (const float*)d_in[3];
    const float* W1   = (const float*)d_in[4];
    const float* b1   = (const float*)d_in[5];
    const float* W2   = (const float*)d_in[6];
    const float* b2   = (const float*)d_in[7];
    float* out   = (float*)d_out;
    float* probs = out + (size_t)Nn * Dd;

    float* g_H_ptr;
    cudaGetSymbolAddress((void**)&g_H_ptr, g_H);

    zero_kernel<<<(Nn * Dd / 4 + 255) / 256, 256>>>((float4*)out);
    router_kernel<<<Nn / 8, 256>>>(x, grad, Wr, br, probs);
    scan_kernel<<<1, 32>>>();
    scatter_kernel<<<Nn / 256, 256>>>();
    ffn_mma_kernel<1><<<dim3(TILES_MAX, Hh / 128), 256>>>(x, W1, b1, g_H_ptr);
    ffn_mma_kernel<2><<<dim3(TILES_MAX, Dd / 128), 256>>>(g_H_ptr, W2, b2, out);
}

// round 5
// speedup vs baseline: 2.7114x; 1.0769x over previous
#include <cuda_runtime.h>
#include <cuda_bf16.h>
#include <math.h>

#define Nn 32768
#define Dd 256
#define Ee 8
#define Hh 1024
#define MT 128
#define TILES_MAX (Nn * 2 / MT + Ee)   // 520
#define HROWS (Nn * 2 + MT)            // 65664

typedef unsigned short u16;
typedef unsigned int u32;
typedef unsigned long long u64;

// ---------------- device scratch (static, no allocation) ----------------
__device__ int   g_counts[Ee];
__device__ int   g_cursor[Ee];
__device__ int   g_off[Ee + 1];
__device__ int   g_tileoff[Ee + 1];
__device__ int   g_tok_e[Nn];
__device__ float g_tok_p1[Nn];
__device__ float g_tok_p2[Nn];
__device__ int   g_gtok[Nn * 2];
__device__ float g_gp[Nn * 2];

__device__ u16 g_Xh[Nn * Dd],  g_Xl[Nn * Dd];              // split X [n][k]
__device__ u16 g_W1h[Ee * Dd * Hh], g_W1l[Ee * Dd * Hh];   // split W1 [e][k=256][n=1024]
__device__ u16 g_W2h[Ee * Dd * Hh], g_W2l[Ee * Dd * Hh];   // split W2 [e][k=1024][n=256]
__device__ u16 g_HhA[(size_t)HROWS * Hh], g_HlA[(size_t)HROWS * Hh];  // split hidden

// ---------------- helpers ----------------
__device__ __forceinline__ u32 smem_u32(const void* p) {
    return (u32)__cvta_generic_to_shared(p);
}
__device__ __forceinline__ void hilo2(float a, float b, u32& hi, u32& lo) {
    __nv_bfloat16 ha = __float2bfloat16_rn(a), hb = __float2bfloat16_rn(b);
    float ra = a - __bfloat162float(ha);
    float rb = b - __bfloat162float(hb);
    __nv_bfloat16 la = __float2bfloat16_rn(ra), lb = __float2bfloat16_rn(rb);
    hi = (u32)__bfloat16_as_ushort(ha) | ((u32)__bfloat16_as_ushort(hb) << 16);
    lo = (u32)__bfloat16_as_ushort(la) | ((u32)__bfloat16_as_ushort(lb) << 16);
}
__device__ __forceinline__ float gelu_exact(float v) {
    return 0.5f * v * (1.f + erff(v * 0.70710678118654752f));
}
#define CP16(dst, src) \
    asm volatile("cp.async.cg.shared.global [%0],[%1],16;" ::"r"(dst), "l"(src))
#define CPCOMMIT() asm volatile("cp.async.commit_group;" ::: "memory")
template <int N> __device__ __forceinline__ void cp_wait() {
    asm volatile("cp.async.wait_group %0;" ::"n"(N) : "memory");
}
__device__ __forceinline__ void ldm4(u32 addr, u32& r0, u32& r1, u32& r2, u32& r3) {
    asm volatile("ldmatrix.sync.aligned.m8n8.x4.shared.b16 {%0,%1,%2,%3},[%4];"
                 : "=r"(r0), "=r"(r1), "=r"(r2), "=r"(r3) : "r"(addr));
}
__device__ __forceinline__ void ldm4t(u32 addr, u32& r0, u32& r1, u32& r2, u32& r3) {
    asm volatile("ldmatrix.sync.aligned.m8n8.x4.trans.shared.b16 {%0,%1,%2,%3},[%4];"
                 : "=r"(r0), "=r"(r1), "=r"(r2), "=r"(r3) : "r"(addr));
}
__device__ __forceinline__ void mma16816(float* c, u32 a0, u32 a1, u32 a2, u32 a3,
                                         u32 b0, u32 b1) {
    asm volatile(
        "mma.sync.aligned.m16n8k16.row.col.f32.bf16.bf16.f32 "
        "{%0,%1,%2,%3},{%4,%5,%6,%7},{%8,%9},{%0,%1,%2,%3};"
        : "+f"(c[0]), "+f"(c[1]), "+f"(c[2]), "+f"(c[3])
        : "r"(a0), "r"(a1), "r"(a2), "r"(a3), "r"(b0), "r"(b1));
}

// ---------------- kernel 0: zero out + counters ----------------
__global__ void zero_kernel(float4* out4) {
    int i = blockIdx.x * blockDim.x + threadIdx.x;
    if (i < (Nn * Dd / 4)) out4[i] = make_float4(0.f, 0.f, 0.f, 0.f);
    if (blockIdx.x == 0 && threadIdx.x < Ee) {
        g_counts[threadIdx.x] = 0;
        g_cursor[threadIdx.x] = 0;
    }
}

// ---------------- generic fp32 -> bf16 hi/lo split ----------------
__global__ void split_kernel(const float4* __restrict__ src,
                             u16* __restrict__ dh, u16* __restrict__ dl, int n4) {
    int i = blockIdx.x * 256 + threadIdx.x;
    if (i >= n4) return;
    float4 v = src[i];
    u32 h0, l0, h1, l1;
    hilo2(v.x, v.y, h0, l0);
    hilo2(v.z, v.w, h1, l1);
    *(uint2*)&dh[(size_t)i * 4] = make_uint2(h0, h1);
    *(uint2*)&dl[(size_t)i * 4] = make_uint2(l0, l1);
}

// ---------------- kernel 1: router ----------------
__global__ void router_kernel(const float* __restrict__ x,
                              const float* __restrict__ grad,
                              const float* __restrict__ Wr,
                              const float* __restrict__ br,
                              float* __restrict__ probs_out) {
    __shared__ float WrT[Ee][Dd + 1];
    int tid = threadIdx.x;
    for (int i = tid; i < (Dd + 1) * Ee; i += blockDim.x) {
        int d = i >> 3, e = i & 7;
        WrT[e][d] = Wr[i];
    }
    __syncthreads();

    int wid = tid >> 5, lane = tid & 31;
    int n = blockIdx.x * 8 + wid;
    const float* xr = x + (size_t)n * Dd;

    float a[8];
#pragma unroll
    for (int e = 0; e < 8; e++) a[e] = 0.f;
#pragma unroll
    for (int j = 0; j < 8; j++) {
        float xv = xr[lane + 32 * j];
#pragma unroll
        for (int e = 0; e < 8; e++) a[e] += xv * WrT[e][lane + 32 * j];
    }
#pragma unroll
    for (int off = 16; off > 0; off >>= 1) {
#pragma unroll
        for (int e = 0; e < 8; e++) a[e] += __shfl_xor_sync(0xffffffffu, a[e], off);
    }

    if (lane == 0) {
        float g = grad[n];
        float p[8];
        float m = -1e30f;
#pragma unroll
        for (int e = 0; e < 8; e++) {
            p[e] = a[e] + g * WrT[e][Dd] + br[e];
            m = fmaxf(m, p[e]);
        }
        float s = 0.f;
#pragma unroll
        for (int e = 0; e < 8; e++) { p[e] = expf(p[e] - m); s += p[e]; }
        float inv = 1.f / s;
#pragma unroll
        for (int e = 0; e < 8; e++) {
            p[e] *= inv;
            probs_out[(size_t)n * 8 + e] = p[e];
        }
        int e1 = 0;
#pragma unroll
        for (int e = 1; e < 8; e++) if (p[e] > p[e1]) e1 = e;
        int e2 = (e1 == 0) ? 1 : 0;
#pragma unroll
        for (int e = 0; e < 8; e++) if (e != e1 && p[e] > p[e2]) e2 = e;

        g_tok_e[n]  = e1 | (e2 << 8);
        g_tok_p1[n] = p[e1];
        g_tok_p2[n] = p[e2];
        atomicAdd(&g_counts[e1], 1);
        atomicAdd(&g_counts[e2], 1);
    }
}

// ---------------- kernel 2: tiny scan ----------------
__global__ void scan_kernel() {
    if (threadIdx.x == 0) {
        int o = 0, t = 0;
#pragma unroll
        for (int e = 0; e < Ee; e++) {
            g_off[e] = o;
            g_tileoff[e] = t;
            o += g_counts[e];
            t += (g_counts[e] + MT - 1) / MT;
        }
        g_off[Ee] = o;
        g_tileoff[Ee] = t;
    }
}

// ---------------- kernel 3: scatter ----------------
__global__ void scatter_kernel() {
    int n = blockIdx.x * blockDim.x + threadIdx.x;
    if (n >= Nn) return;
    int pk = g_tok_e[n];
    int e1 = pk & 255, e2 = (pk >> 8) & 255;
    int i1 = g_off[e1] + atomicAdd(&g_cursor[e1], 1);
    g_gtok[i1] = n; g_gp[i1] = g_tok_p1[n];
    int i2 = g_off[e2] + atomicAdd(&g_cursor[e2], 1);
    g_gtok[i2] = n; g_gp[i2] = g_tok_p2[n];
}

// ---------------- FFN mma.sync kernels, double-buffered cp.async ----------------
// stage layout (bytes from stage base):
//   Ah [128][40]u16 @0       (10240 B)   Al @10240
//   Bh [32][136]u16 @20480   ( 8704 B)   Bl @29184
// stage size 37888 B, two stages -> 75776 B dynamic smem
#define STG 37888
#define A_L 10240
#define B_H 20480
#define B_L 29184
#define DYN_SMEM (2 * STG + 16)

template <int PASS>
__device__ __forceinline__ void load_stage(int tid, u32 st, int kofs,
                                           int e, int ncs, int row0, const int* s_tok) {
    constexpr int KD = (PASS == 1) ? Dd : Hh;
    constexpr int ND = (PASS == 1) ? Hh : Dd;
    const u16* Ah = (PASS == 1) ? g_Xh : g_HhA;
    const u16* Al = (PASS == 1) ? g_Xl : g_HlA;
    const u16* Bh = (PASS == 1) ? g_W1h : g_W2h;
    const u16* Bl = (PASS == 1) ? g_W1l : g_W2l;
#pragma unroll
    for (int i = 0; i < 2; i++) {           // A: 512 16B chunks (hi), + lo
        int idx = tid + 256 * i;
        int row = idx >> 2, c = idx & 3;
        u32 d = st + row * 80 + c * 16;
        size_t g;
        if (PASS == 1) g = (size_t)s_tok[row] * Dd + kofs + c * 8;
        else           g = (size_t)(row0 + row) * Hh + kofs + c * 8;
        CP16(d, Ah + g);
        CP16(d + A_L, Al + g);
    }
#pragma unroll
    for (int i = 0; i < 2; i++) {           // B: 512 16B chunks (hi), + lo
        int idx = tid + 256 * i;
        int row = idx >> 4, c = idx & 15;
        u32 d = st + B_H + row * 272 + c * 16;
        size_t g = ((size_t)e * KD + kofs + row) * ND + ncs + c * 8;
        CP16(d, Bh + g);
        CP16(d + (B_L - B_H), Bl + g);
    }
}

template <int PASS>
__global__ void __launch_bounds__(256, 1)
ffn_mma_kernel(const float* __restrict__ bias, float* __restrict__ dst) {
    constexpr int KD = (PASS == 1) ? Dd : Hh;
    constexpr int ND = (PASS == 1) ? Hh : Dd;
    constexpr int KS = KD / 32;

    extern __shared__ char dsm[];
    u32 base = (smem_u32(dsm) + 15) & ~15u;
    __shared__ int   s_tok[MT];
    __shared__ float s_p[MT];

    int b = blockIdx.x;
    if (b >= g_tileoff[Ee]) return;
    int e = 0;
#pragma unroll
    for (int i = 1; i < Ee; i++) if (b >= g_tileoff[i]) e = i;
    int tile  = b - g_tileoff[e];
    int row0  = g_off[e] + tile * MT;
    int nrows = min(MT, g_off[e + 1] - row0);
    int ncs   = blockIdx.y * 128;

    int tid = threadIdx.x;
    if (tid < MT) {
        if (tid < nrows) { s_tok[tid] = g_gtok[row0 + tid]; s_p[tid] = g_gp[row0 + tid]; }
        else             { s_tok[tid] = 0;                  s_p[tid] = 0.f; }
    }
    __syncthreads();

    int wid = tid >> 5, lane = tid & 31;
    int wm = wid >> 2, wn = wid & 3;
    int m0 = wm * 64, n0w = wn * 32;
    int lr = lane & 15, lc = (lane >> 4) << 3;

    float acc[4][4][4];
#pragma unroll
    for (int mi = 0; mi < 4; mi++)
#pragma unroll
        for (int ni = 0; ni < 4; ni++)
#pragma unroll
            for (int j = 0; j < 4; j++) acc[mi][ni][j] = 0.f;

    load_stage<PASS>(tid, base, 0, e, ncs, row0, s_tok);
    CPCOMMIT();

    for (int ks = 0; ks < KS; ks++) {
        u32 st = base + (u32)(ks & 1) * STG;
        if (ks + 1 < KS) {
            load_stage<PASS>(tid, base + (u32)((ks + 1) & 1) * STG,
                             (ks + 1) * 32, e, ncs, row0, s_tok);
            CPCOMMIT();
            cp_wait<1>();
        } else {
            cp_wait<0>();
        }
        __syncthreads();
#pragma unroll
        for (int k16 = 0; k16 < 2; k16++) {
            u32 ah[4][4], al_[4][4], bh[4][2], bl[4][2];
#pragma unroll
            for (int mi = 0; mi < 4; mi++) {
                u32 arow = st + (u32)(m0 + mi * 16 + lr) * 80 + (u32)(k16 * 16 + lc) * 2;
                ldm4(arow, ah[mi][0], ah[mi][1], ah[mi][2], ah[mi][3]);
                ldm4(arow + A_L, al_[mi][0], al_[mi][1], al_[mi][2], al_[mi][3]);
            }
#pragma unroll
            for (int nj = 0; nj < 2; nj++) {
                u32 brow = st + B_H + (u32)(k16 * 16 + lr) * 272
                         + (u32)(n0w + nj * 16 + lc) * 2;
                ldm4t(brow, bh[2 * nj][0], bh[2 * nj][1], bh[2 * nj + 1][0], bh[2 * nj + 1][1]);
                ldm4t(brow + (B_L - B_H),
                      bl[2 * nj][0], bl[2 * nj][1], bl[2 * nj + 1][0], bl[2 * nj + 1][1]);
            }
#pragma unroll
            for (int mi = 0; mi < 4; mi++)
#pragma unroll
                for (int ni = 0; ni < 4; ni++) {
                    mma16816(acc[mi][ni], ah[mi][0], ah[mi][1], ah[mi][2], ah[mi][3],
                             bh[ni][0], bh[ni][1]);
                    mma16816(acc[mi][ni], ah[mi][0], ah[mi][1], ah[mi][2], ah[mi][3],
                             bl[ni][0], bl[ni][1]);
                    mma16816(acc[mi][ni], al_[mi][0], al_[mi][1], al_[mi][2], al_[mi][3],
                             bh[ni][0], bh[ni][1]);
                }
        }
        __syncthreads();
    }

    // ---- epilogue ----
    int gr = lane >> 2, gc = (lane & 3) * 2;
    const float* be = bias + (size_t)e * ND;
#pragma unroll
    for (int mi = 0; mi < 4; mi++) {
        int r1 = m0 + mi * 16 + gr;
        int r2 = r1 + 8;
#pragma unroll
        for (int ni = 0; ni < 4; ni++) {
            int col = ncs + n0w + ni * 8 + gc;
            float bv0 = be[col], bv1 = be[col + 1];
            if (PASS == 1) {
                if (r1 < nrows) {
                    float v0 = gelu_exact(acc[mi][ni][0] + bv0);
                    float v1 = gelu_exact(acc[mi][ni][1] + bv1);
                    u32 hi, lo; hilo2(v0, v1, hi, lo);
                    size_t hbp = (size_t)(row0 + r1) * Hh + col;
                    *(u32*)&g_HhA[hbp] = hi;
                    *(u32*)&g_HlA[hbp] = lo;
                }
                if (r2 < nrows) {
                    float v0 = gelu_exact(acc[mi][ni][2] + bv0);
                    float v1 = gelu_exact(acc[mi][ni][3] + bv1);
                    u32 hi, lo; hilo2(v0, v1, hi, lo);
                    size_t hbp = (size_t)(row0 + r2) * Hh + col;
                    *(u32*)&g_HhA[hbp] = hi;
                    *(u32*)&g_HlA[hbp] = lo;
                }
            } else {
                if (r1 < nrows) {
                    float p = s_p[r1];
                    float* orow = dst + (size_t)s_tok[r1] * Dd;
                    atomicAdd(orow + col,     (acc[mi][ni][0] + bv0) * p);
                    atomicAdd(orow + col + 1, (acc[mi][ni][1] + bv1) * p);
                }
                if (r2 < nrows) {
                    float p = s_p[r2];
                    float* orow = dst + (size_t)s_tok[r2] * Dd;
                    atomicAdd(orow + col,     (acc[mi][ni][2] + bv0) * p);
                    atomicAdd(orow + col + 1, (acc[mi][ni][3] + bv1) * p);
                }
            }
        }
    }
}

// ---------------- launcher ----------------
extern "C" void kernel_launch(void* const* d_in, const int* in_sizes, int n_in,
                              void* d_out, int out_size) {
    const float* x    = (const float*)d_in[0];
    const float* grad = (const float*)d_in[1];
    const float* Wr   = (const float*)d_in[2];
    const float* br   = (const float*)d_in[3];
    const float* W1   = (const float*)d_in[4];
    const float* b1   = (const float*)d_in[5];
    const float* W2   = (const float*)d_in[6];
    const float* b2   = (const float*)d_in[7];
    float* out   = (float*)d_out;
    float* probs = out + (size_t)Nn * Dd;

    u16 *xh, *xl, *w1h, *w1l, *w2h, *w2l;
    cudaGetSymbolAddress((void**)&xh,  g_Xh);
    cudaGetSymbolAddress((void**)&xl,  g_Xl);
    cudaGetSymbolAddress((void**)&w1h, g_W1h);
    cudaGetSymbolAddress((void**)&w1l, g_W1l);
    cudaGetSymbolAddress((void**)&w2h, g_W2h);
    cudaGetSymbolAddress((void**)&w2l, g_W2l);

    cudaFuncSetAttribute(ffn_mma_kernel<1>,
                         cudaFuncAttributeMaxDynamicSharedMemorySize, DYN_SMEM);
    cudaFuncSetAttribute(ffn_mma_kernel<2>,
                         cudaFuncAttributeMaxDynamicSharedMemorySize, DYN_SMEM);

    zero_kernel<<<(Nn * Dd / 4 + 255) / 256, 256>>>((float4*)out);
    split_kernel<<<Nn * Dd / 4 / 256, 256>>>((const float4*)x, xh, xl, Nn * Dd / 4);
    split_kernel<<<Ee * Dd * Hh / 4 / 256, 256>>>((const float4*)W1, w1h, w1l, Ee * Dd * Hh / 4);
    split_kernel<<<Ee * Dd * Hh / 4 / 256, 256>>>((const float4*)W2, w2h, w2l, Ee * Dd * Hh / 4);
    router_kernel<<<Nn / 8, 256>>>(x, grad, Wr, br, probs);
    scan_kernel<<<1, 32>>>();
    scatter_kernel<<<Nn / 256, 256>>>();
    ffn_mma_kernel<1><<<dim3(TILES_MAX, Hh / 128), 256, DYN_SMEM>>>(b1, nullptr);
    ffn_mma_kernel<2><<<dim3(TILES_MAX, Dd / 128), 256, DYN_SMEM>>>(b2, out);
}

// round 8
// speedup vs baseline: 3.5144x; 1.2962x over previous
#include <cuda_runtime.h>
#include <cuda_fp16.h>
#include <math.h>

#define Nn 32768
#define Dd 256
#define Ee 8
#define Hh 1024
#define MT 128
#define TILES_MAX (Nn * 2 / MT + Ee)   // 520
#define HROWS (Nn * 2 + MT)            // 65664
#define XN4 (Nn * Dd / 4)              // 2097152
#define WN4 (Ee * Dd * Hh / 4)         // 524288

typedef unsigned short u16;
typedef unsigned int u32;
typedef unsigned long long u64;

// ---------------- device scratch (static, no allocation) ----------------
__device__ int   g_counts[Ee];
__device__ int   g_cursor[Ee];
__device__ int   g_off[Ee + 1];
__device__ int   g_tileoff[Ee + 1];
__device__ int   g_tok_e[Nn];
__device__ float g_tok_p1[Nn];
__device__ float g_tok_p2[Nn];
__device__ int   g_gtok[Nn * 2];
__device__ float g_gp[Nn * 2];

__device__ u16 g_Xf[Nn * Dd];                              // X as fp16 [n][k]
__device__ u16 g_W1h[Ee * Dd * Hh], g_W1l[Ee * Dd * Hh];   // W1 fp16 hi/lo [e][k=256][n=1024]
__device__ u16 g_W2h[Ee * Dd * Hh], g_W2l[Ee * Dd * Hh];   // W2 fp16 hi/lo [e][k=1024][n=256]
__device__ u16 g_Hf[(size_t)HROWS * Hh];                   // hidden as fp16

// ---------------- helpers ----------------
__device__ __forceinline__ u32 smem_u32(const void* p) {
    return (u32)__cvta_generic_to_shared(p);
}
__device__ __forceinline__ u32 pack_half2(float a, float b) {
    __half ha = __float2half_rn(a), hb = __float2half_rn(b);
    return (u32)__half_as_ushort(ha) | ((u32)__half_as_ushort(hb) << 16);
}
__device__ __forceinline__ void hilo2_f16(float a, float b, u32& hi, u32& lo) {
    __half ha = __float2half_rn(a), hb = __float2half_rn(b);
    float ra = a - __half2float(ha);
    float rb = b - __half2float(hb);
    __half la = __float2half_rn(ra), lb = __float2half_rn(rb);
    hi = (u32)__half_as_ushort(ha) | ((u32)__half_as_ushort(hb) << 16);
    lo = (u32)__half_as_ushort(la) | ((u32)__half_as_ushort(lb) << 16);
}
__device__ __forceinline__ float gelu_exact(float v) {
    return 0.5f * v * (1.f + erff(v * 0.70710678118654752f));
}
#define CP16(dst, src) \
    asm volatile("cp.async.cg.shared.global [%0],[%1],16;" ::"r"(dst), "l"(src))
#define CPCOMMIT() asm volatile("cp.async.commit_group;" ::: "memory")
template <int N> __device__ __forceinline__ void cp_wait() {
    asm volatile("cp.async.wait_group %0;" ::"n"(N) : "memory");
}
__device__ __forceinline__ void ldm4(u32 addr, u32& r0, u32& r1, u32& r2, u32& r3) {
    asm volatile("ldmatrix.sync.aligned.m8n8.x4.shared.b16 {%0,%1,%2,%3},[%4];"
                 : "=r"(r0), "=r"(r1), "=r"(r2), "=r"(r3) : "r"(addr));
}
__device__ __forceinline__ void ldm4t(u32 addr, u32& r0, u32& r1, u32& r2, u32& r3) {
    asm volatile("ldmatrix.sync.aligned.m8n8.x4.trans.shared.b16 {%0,%1,%2,%3},[%4];"
                 : "=r"(r0), "=r"(r1), "=r"(r2), "=r"(r3) : "r"(addr));
}
__device__ __forceinline__ void mma16816(float* c, u32 a0, u32 a1, u32 a2, u32 a3,
                                         u32 b0, u32 b1) {
    asm volatile(
        "mma.sync.aligned.m16n8k16.row.col.f32.f16.f16.f32 "
        "{%0,%1,%2,%3},{%4,%5,%6,%7},{%8,%9},{%0,%1,%2,%3};"
        : "+f"(c[0]), "+f"(c[1]), "+f"(c[2]), "+f"(c[3])
        : "r"(a0), "r"(a1), "r"(a2), "r"(a3), "r"(b0), "r"(b1));
}

// ---------------- kernel 0: zero out + counters ----------------
__global__ void zero_kernel(float4* out4) {
    int i = blockIdx.x * blockDim.x + threadIdx.x;
    if (i < (Nn * Dd / 4)) out4[i] = make_float4(0.f, 0.f, 0.f, 0.f);
    if (blockIdx.x == 0 && threadIdx.x < Ee) {
        g_counts[threadIdx.x] = 0;
        g_cursor[threadIdx.x] = 0;
    }
}

// ---------------- kernel 1: convert X -> fp16, W1/W2 -> fp16 hi/lo ----------------
__global__ void cvt_kernel(const float4* __restrict__ x4,
                           const float4* __restrict__ w14,
                           const float4* __restrict__ w24) {
    int i = blockIdx.x * 256 + threadIdx.x;
    if (i < XN4) {
        float4 v = x4[i];
        *(uint2*)&g_Xf[(size_t)i * 4] =
            make_uint2(pack_half2(v.x, v.y), pack_half2(v.z, v.w));
    } else if (i < XN4 + WN4) {
        int j = i - XN4;
        float4 v = w14[j];
        u32 h0, l0, h1, l1;
        hilo2_f16(v.x, v.y, h0, l0);
        hilo2_f16(v.z, v.w, h1, l1);
        *(uint2*)&g_W1h[(size_t)j * 4] = make_uint2(h0, h1);
        *(uint2*)&g_W1l[(size_t)j * 4] = make_uint2(l0, l1);
    } else {
        int j = i - XN4 - WN4;
        float4 v = w24[j];
        u32 h0, l0, h1, l1;
        hilo2_f16(v.x, v.y, h0, l0);
        hilo2_f16(v.z, v.w, h1, l1);
        *(uint2*)&g_W2h[(size_t)j * 4] = make_uint2(h0, h1);
        *(uint2*)&g_W2l[(size_t)j * 4] = make_uint2(l0, l1);
    }
}

// ---------------- kernel 2: router (fp32, exact selection) ----------------
__global__ void router_kernel(const float* __restrict__ x,
                              const float* __restrict__ grad,
                              const float* __restrict__ Wr,
                              const float* __restrict__ br,
                              float* __restrict__ probs_out) {
    __shared__ float WrT[Ee][Dd + 1];
    int tid = threadIdx.x;
    for (int i = tid; i < (Dd + 1) * Ee; i += blockDim.x) {
        int d = i >> 3, e = i & 7;
        WrT[e][d] = Wr[i];
    }
    __syncthreads();

    int wid = tid >> 5, lane = tid & 31;
    int n = blockIdx.x * 8 + wid;
    const float* xr = x + (size_t)n * Dd;

    float a[8];
#pragma unroll
    for (int e = 0; e < 8; e++) a[e] = 0.f;
#pragma unroll
    for (int j = 0; j < 8; j++) {
        float xv = xr[lane + 32 * j];
#pragma unroll
        for (int e = 0; e < 8; e++) a[e] += xv * WrT[e][lane + 32 * j];
    }
#pragma unroll
    for (int off = 16; off > 0; off >>= 1) {
#pragma unroll
        for (int e = 0; e < 8; e++) a[e] += __shfl_xor_sync(0xffffffffu, a[e], off);
    }

    if (lane == 0) {
        float g = grad[n];
        float p[8];
        float m = -1e30f;
#pragma unroll
        for (int e = 0; e < 8; e++) {
            p[e] = a[e] + g * WrT[e][Dd] + br[e];
            m = fmaxf(m, p[e]);
        }
        float s = 0.f;
#pragma unroll
        for (int e = 0; e < 8; e++) { p[e] = expf(p[e] - m); s += p[e]; }
        float inv = 1.f / s;
#pragma unroll
        for (int e = 0; e < 8; e++) {
            p[e] *= inv;
            probs_out[(size_t)n * 8 + e] = p[e];
        }
        int e1 = 0;
#pragma unroll
        for (int e = 1; e < 8; e++) if (p[e] > p[e1]) e1 = e;
        int e2 = (e1 == 0) ? 1 : 0;
#pragma unroll
        for (int e = 0; e < 8; e++) if (e != e1 && p[e] > p[e2]) e2 = e;

        g_tok_e[n]  = e1 | (e2 << 8);
        g_tok_p1[n] = p[e1];
        g_tok_p2[n] = p[e2];
        atomicAdd(&g_counts[e1], 1);
        atomicAdd(&g_counts[e2], 1);
    }
}

// ---------------- kernel 3: tiny scan ----------------
__global__ void scan_kernel() {
    if (threadIdx.x == 0) {
        int o = 0, t = 0;
#pragma unroll
        for (int e = 0; e < Ee; e++) {
            g_off[e] = o;
            g_tileoff[e] = t;
            o += g_counts[e];
            t += (g_counts[e] + MT - 1) / MT;
        }
        g_off[Ee] = o;
        g_tileoff[Ee] = t;
    }
}

// ---------------- kernel 4: scatter ----------------
__global__ void scatter_kernel() {
    int n = blockIdx.x * blockDim.x + threadIdx.x;
    if (n >= Nn) return;
    int pk = g_tok_e[n];
    int e1 = pk & 255, e2 = (pk >> 8) & 255;
    int i1 = g_off[e1] + atomicAdd(&g_cursor[e1], 1);
    g_gtok[i1] = n; g_gp[i1] = g_tok_p1[n];
    int i2 = g_off[e2] + atomicAdd(&g_cursor[e2], 1);
    g_gtok[i2] = n; g_gp[i2] = g_tok_p2[n];
}

// ---------------- FFN mma.sync kernels (2-term fp16), double-buffered ----------------
// stage layout (bytes from stage base):
//   A  [128][40]u16 @0       (10240 B)
//   Bh [32][136]u16 @10240   ( 8704 B)
//   Bl [32][136]u16 @18944   ( 8704 B)
// stage 27648 B, 2 stages = 55296 B dynamic smem
#define STG 27648
#define B_H 10240
#define B_L 18944
#define DYN_SMEM (2 * STG + 16)

template <int PASS>
__device__ __forceinline__ void load_stage(int tid, u32 st, int kofs,
                                           int e, int ncs, int row0, const int* s_tok) {
    constexpr int KD = (PASS == 1) ? Dd : Hh;
    constexpr int ND = (PASS == 1) ? Hh : Dd;
    const u16* Af = (PASS == 1) ? g_Xf : g_Hf;
    const u16* Bh = (PASS == 1) ? g_W1h : g_W2h;
    const u16* Bl = (PASS == 1) ? g_W1l : g_W2l;
#pragma unroll
    for (int i = 0; i < 2; i++) {           // A: 512 16B chunks
        int idx = tid + 256 * i;
        int row = idx >> 2, c = idx & 3;
        u32 d = st + row * 80 + c * 16;
        size_t g;
        if (PASS == 1) g = (size_t)s_tok[row] * Dd + kofs + c * 8;
        else           g = (size_t)(row0 + row) * Hh + kofs + c * 8;
        CP16(d, Af + g);
    }
#pragma unroll
    for (int i = 0; i < 2; i++) {           // B: 512 16B chunks (hi) + 512 (lo)
        int idx = tid + 256 * i;
        int row = idx >> 4, c = idx & 15;
        u32 d = st + B_H + row * 272 + c * 16;
        size_t g = ((size_t)e * KD + kofs + row) * ND + ncs + c * 8;
        CP16(d, Bh + g);
        CP16(d + (B_L - B_H), Bl + g);
    }
}

template <int PASS>
__global__ void __launch_bounds__(256, 1)
ffn_mma_kernel(const float* __restrict__ bias, float* __restrict__ dst) {
    constexpr int KD = (PASS == 1) ? Dd : Hh;
    constexpr int ND = (PASS == 1) ? Hh : Dd;
    constexpr int KS = KD / 32;

    extern __shared__ char dsm[];
    u32 base = (smem_u32(dsm) + 15) & ~15u;
    __shared__ int   s_tok[MT];
    __shared__ float s_p[MT];

    int b = blockIdx.x;
    if (b >= g_tileoff[Ee]) return;
    int e = 0;
#pragma unroll
    for (int i = 1; i < Ee; i++) if (b >= g_tileoff[i]) e = i;
    int tile  = b - g_tileoff[e];
    int row0  = g_off[e] + tile * MT;
    int nrows = min(MT, g_off[e + 1] - row0);
    int ncs   = blockIdx.y * 128;

    int tid = threadIdx.x;
    if (tid < MT) {
        if (tid < nrows) { s_tok[tid] = g_gtok[row0 + tid]; s_p[tid] = g_gp[row0 + tid]; }
        else             { s_tok[tid] = 0;                  s_p[tid] = 0.f; }
    }
    __syncthreads();

    int wid = tid >> 5, lane = tid & 31;
    int wm = wid >> 2, wn = wid & 3;
    int m0 = wm * 64, n0w = wn * 32;
    int lr = lane & 15, lc = (lane >> 4) << 3;

    float acc[4][4][4];
#pragma unroll
    for (int mi = 0; mi < 4; mi++)
#pragma unroll
        for (int ni = 0; ni < 4; ni++)
#pragma unroll
            for (int j = 0; j < 4; j++) acc[mi][ni][j] = 0.f;

    load_stage<PASS>(tid, base, 0, e, ncs, row0, s_tok);
    CPCOMMIT();

    for (int ks = 0; ks < KS; ks++) {
        u32 st = base + (u32)(ks & 1) * STG;
        if (ks + 1 < KS) {
            load_stage<PASS>(tid, base + (u32)((ks + 1) & 1) * STG,
                             (ks + 1) * 32, e, ncs, row0, s_tok);
            CPCOMMIT();
            cp_wait<1>();
        } else {
            cp_wait<0>();
        }
        __syncthreads();
#pragma unroll
        for (int k16 = 0; k16 < 2; k16++) {
            u32 a[4][4], bh[4][2], bl[4][2];
#pragma unroll
            for (int mi = 0; mi < 4; mi++) {
                u32 arow = st + (u32)(m0 + mi * 16 + lr) * 80 + (u32)(k16 * 16 + lc) * 2;
                ldm4(arow, a[mi][0], a[mi][1], a[mi][2], a[mi][3]);
            }
#pragma unroll
            for (int nj = 0; nj < 2; nj++) {
                u32 brow = st + B_H + (u32)(k16 * 16 + lr) * 272
                         + (u32)(n0w + nj * 16 + lc) * 2;
                ldm4t(brow, bh[2 * nj][0], bh[2 * nj][1], bh[2 * nj + 1][0], bh[2 * nj + 1][1]);
                ldm4t(brow + (B_L - B_H),
                      bl[2 * nj][0], bl[2 * nj][1], bl[2 * nj + 1][0], bl[2 * nj + 1][1]);
            }
#pragma unroll
            for (int mi = 0; mi < 4; mi++)
#pragma unroll
                for (int ni = 0; ni < 4; ni++) {
                    mma16816(acc[mi][ni], a[mi][0], a[mi][1], a[mi][2], a[mi][3],
                             bh[ni][0], bh[ni][1]);
                    mma16816(acc[mi][ni], a[mi][0], a[mi][1], a[mi][2], a[mi][3],
                             bl[ni][0], bl[ni][1]);
                }
        }
        __syncthreads();
    }

    // ---- epilogue ----
    int gr = lane >> 2, gc = (lane & 3) * 2;
    const float* be = bias + (size_t)e * ND;
#pragma unroll
    for (int mi = 0; mi < 4; mi++) {
        int r1 = m0 + mi * 16 + gr;
        int r2 = r1 + 8;
#pragma unroll
        for (int ni = 0; ni < 4; ni++) {
            int col = ncs + n0w + ni * 8 + gc;
            float bv0 = be[col], bv1 = be[col + 1];
            if (PASS == 1) {
                if (r1 < nrows) {
                    float v0 = gelu_exact(acc[mi][ni][0] + bv0);
                    float v1 = gelu_exact(acc[mi][ni][1] + bv1);
                    *(u32*)&g_Hf[(size_t)(row0 + r1) * Hh + col] = pack_half2(v0, v1);
                }
                if (r2 < nrows) {
                    float v0 = gelu_exact(acc[mi][ni][2] + bv0);
                    float v1 = gelu_exact(acc[mi][ni][3] + bv1);
                    *(u32*)&g_Hf[(size_t)(row0 + r2) * Hh + col] = pack_half2(v0, v1);
                }
            } else {
                if (r1 < nrows) {
                    float p = s_p[r1];
                    float* orow = dst + (size_t)s_tok[r1] * Dd;
                    atomicAdd(orow + col,     (acc[mi][ni][0] + bv0) * p);
                    atomicAdd(orow + col + 1, (acc[mi][ni][1] + bv1) * p);
                }
                if (r2 < nrows) {
                    float p = s_p[r2];
                    float* orow = dst + (size_t)s_tok[r2] * Dd;
                    atomicAdd(orow + col,     (acc[mi][ni][2] + bv0) * p);
                    atomicAdd(orow + col + 1, (acc[mi][ni][3] + bv1) * p);
                }
            }
        }
    }
}

// ---------------- launcher ----------------
extern "C" void kernel_launch(void* const* d_in, const int* in_sizes, int n_in,
                              void* d_out, int out_size) {
    const float* x    = (const float*)d_in[0];
    const float* grad = (const float*)d_in[1];
    const float* Wr   = (const float*)d_in[2];
    const float* br   = (const float*)d_in[3];
    const float* W1   = (const float*)d_in[4];
    const float* b1   = (const float*)d_in[5];
    const float* W2   = (const float*)d_in[6];
    const float* b2   = (const float*)d_in[7];
    float* out   = (float*)d_out;
    float* probs = out + (size_t)Nn * Dd;

    cudaFuncSetAttribute(ffn_mma_kernel<1>,
                         cudaFuncAttributeMaxDynamicSharedMemorySize, DYN_SMEM);
    cudaFuncSetAttribute(ffn_mma_kernel<2>,
                         cudaFuncAttributeMaxDynamicSharedMemorySize, DYN_SMEM);

    // launch order: ffn1 is launch #6 (ncu -s 5 -c 1 lands on it)
    zero_kernel<<<(Nn * Dd / 4 + 255) / 256, 256>>>((float4*)out);
    cvt_kernel<<<(XN4 + 2 * WN4) / 256, 256>>>((const float4*)x,
                                               (const float4*)W1, (const float4*)W2);
    router_kernel<<<Nn / 8, 256>>>(x, grad, Wr, br, probs);
    scan_kernel<<<1, 32>>>();
    scatter_kernel<<<Nn / 256, 256>>>();
    ffn_mma_kernel<1><<<dim3(TILES_MAX, Hh / 128), 256, DYN_SMEM>>>(b1, nullptr);
    ffn_mma_kernel<2><<<dim3(TILES_MAX, Dd / 128), 256, DYN_SMEM>>>(b2, out);
}

// round 9
// speedup vs baseline: 4.7067x; 1.3392x over previous
#include <cuda_runtime.h>
#include <cuda_fp16.h>
#include <math.h>

#define Nn 32768
#define Dd 256
#define Ee 8
#define Hh 1024
#define MT 128
#define TILES_MAX (Nn * 2 / MT + Ee)   // 520
#define HROWS (Nn * 2 + MT)            // 65664
#define XN4 (Nn * Dd / 4)              // 2097152
#define WN4 (Ee * Dd * Hh / 4)         // 524288

typedef unsigned short u16;
typedef unsigned int u32;
typedef unsigned long long u64;

// ---------------- device scratch (static, no allocation) ----------------
__device__ int   g_counts[Ee];
__device__ int   g_cursor[Ee];
__device__ int   g_off[Ee + 1];
__device__ int   g_tileoff[Ee + 1];
__device__ int   g_tok_e[Nn];
__device__ float g_tok_p1[Nn];
__device__ float g_tok_p2[Nn];
__device__ int   g_gtok[Nn * 2];
__device__ float g_gp[Nn * 2];

__device__ u16 g_Xf[Nn * Dd];                  // X as fp16 [n][k]
__device__ u16 g_W1f[Ee * Dd * Hh];            // W1 fp16 [e][k=256][n=1024]
__device__ u16 g_W2f[Ee * Dd * Hh];            // W2 fp16 [e][k=1024][n=256]
__device__ u16 g_Hf[(size_t)HROWS * Hh];       // hidden as fp16

// ---------------- helpers ----------------
__device__ __forceinline__ u32 smem_u32(const void* p) {
    return (u32)__cvta_generic_to_shared(p);
}
__device__ __forceinline__ u32 pack_half2(float a, float b) {
    __half ha = __float2half_rn(a), hb = __float2half_rn(b);
    return (u32)__half_as_ushort(ha) | ((u32)__half_as_ushort(hb) << 16);
}
__device__ __forceinline__ float gelu_exact(float v) {
    return 0.5f * v * (1.f + erff(v * 0.70710678118654752f));
}
#define CP16(dst, src) \
    asm volatile("cp.async.cg.shared.global [%0],[%1],16;" ::"r"(dst), "l"(src))
#define CPCOMMIT() asm volatile("cp.async.commit_group;" ::: "memory")
template <int N> __device__ __forceinline__ void cp_wait() {
    asm volatile("cp.async.wait_group %0;" ::"n"(N) : "memory");
}
__device__ __forceinline__ void ldm4(u32 addr, u32& r0, u32& r1, u32& r2, u32& r3) {
    asm volatile("ldmatrix.sync.aligned.m8n8.x4.shared.b16 {%0,%1,%2,%3},[%4];"
                 : "=r"(r0), "=r"(r1), "=r"(r2), "=r"(r3) : "r"(addr));
}
__device__ __forceinline__ void ldm4t(u32 addr, u32& r0, u32& r1, u32& r2, u32& r3) {
    asm volatile("ldmatrix.sync.aligned.m8n8.x4.trans.shared.b16 {%0,%1,%2,%3},[%4];"
                 : "=r"(r0), "=r"(r1), "=r"(r2), "=r"(r3) : "r"(addr));
}
__device__ __forceinline__ void mma16816(float* c, u32 a0, u32 a1, u32 a2, u32 a3,
                                         u32 b0, u32 b1) {
    asm volatile(
        "mma.sync.aligned.m16n8k16.row.col.f32.f16.f16.f32 "
        "{%0,%1,%2,%3},{%4,%5,%6,%7},{%8,%9},{%0,%1,%2,%3};"
        : "+f"(c[0]), "+f"(c[1]), "+f"(c[2]), "+f"(c[3])
        : "r"(a0), "r"(a1), "r"(a2), "r"(a3), "r"(b0), "r"(b1));
}

// ---------------- kernel 0: zero out + counters ----------------
__global__ void zero_kernel(float4* out4) {
    int i = blockIdx.x * blockDim.x + threadIdx.x;
    if (i < (Nn * Dd / 4)) out4[i] = make_float4(0.f, 0.f, 0.f, 0.f);
    if (blockIdx.x == 0 && threadIdx.x < Ee) {
        g_counts[threadIdx.x] = 0;
        g_cursor[threadIdx.x] = 0;
    }
}

// ---------------- kernel 1: convert X / W1 / W2 -> fp16 ----------------
__global__ void cvt_kernel(const float4* __restrict__ x4,
                           const float4* __restrict__ w14,
                           const float4* __restrict__ w24) {
    int i = blockIdx.x * 256 + threadIdx.x;
    float4 v;
    u16* dst;
    int j;
    if (i < XN4)                { v = x4[i];              dst = g_Xf;  j = i; }
    else if (i < XN4 + WN4)     { j = i - XN4;       v = w14[j]; dst = g_W1f; }
    else                        { j = i - XN4 - WN4; v = w24[j]; dst = g_W2f; }
    *(uint2*)&dst[(size_t)j * 4] =
        make_uint2(pack_half2(v.x, v.y), pack_half2(v.z, v.w));
}

// ---------------- kernel 2: router (fp32, exact selection) ----------------
__global__ void router_kernel(const float* __restrict__ x,
                              const float* __restrict__ grad,
                              const float* __restrict__ Wr,
                              const float* __restrict__ br,
                              float* __restrict__ probs_out) {
    __shared__ float WrT[Ee][Dd + 1];
    int tid = threadIdx.x;
    for (int i = tid; i < (Dd + 1) * Ee; i += blockDim.x) {
        int d = i >> 3, e = i & 7;
        WrT[e][d] = Wr[i];
    }
    __syncthreads();

    int wid = tid >> 5, lane = tid & 31;
    int n = blockIdx.x * 8 + wid;
    const float* xr = x + (size_t)n * Dd;

    float a[8];
#pragma unroll
    for (int e = 0; e < 8; e++) a[e] = 0.f;
#pragma unroll
    for (int j = 0; j < 8; j++) {
        float xv = xr[lane + 32 * j];
#pragma unroll
        for (int e = 0; e < 8; e++) a[e] += xv * WrT[e][lane + 32 * j];
    }
#pragma unroll
    for (int off = 16; off > 0; off >>= 1) {
#pragma unroll
        for (int e = 0; e < 8; e++) a[e] += __shfl_xor_sync(0xffffffffu, a[e], off);
    }

    if (lane == 0) {
        float g = grad[n];
        float p[8];
        float m = -1e30f;
#pragma unroll
        for (int e = 0; e < 8; e++) {
            p[e] = a[e] + g * WrT[e][Dd] + br[e];
            m = fmaxf(m, p[e]);
        }
        float s = 0.f;
#pragma unroll
        for (int e = 0; e < 8; e++) { p[e] = expf(p[e] - m); s += p[e]; }
        float inv = 1.f / s;
#pragma unroll
        for (int e = 0; e < 8; e++) {
            p[e] *= inv;
            probs_out[(size_t)n * 8 + e] = p[e];
        }
        int e1 = 0;
#pragma unroll
        for (int e = 1; e < 8; e++) if (p[e] > p[e1]) e1 = e;
        int e2 = (e1 == 0) ? 1 : 0;
#pragma unroll
        for (int e = 0; e < 8; e++) if (e != e1 && p[e] > p[e2]) e2 = e;

        g_tok_e[n]  = e1 | (e2 << 8);
        g_tok_p1[n] = p[e1];
        g_tok_p2[n] = p[e2];
        atomicAdd(&g_counts[e1], 1);
        atomicAdd(&g_counts[e2], 1);
    }
}

// ---------------- kernel 3: tiny scan ----------------
__global__ void scan_kernel() {
    if (threadIdx.x == 0) {
        int o = 0, t = 0;
#pragma unroll
        for (int e = 0; e < Ee; e++) {
            g_off[e] = o;
            g_tileoff[e] = t;
            o += g_counts[e];
            t += (g_counts[e] + MT - 1) / MT;
        }
        g_off[Ee] = o;
        g_tileoff[Ee] = t;
    }
}

// ---------------- kernel 4: scatter ----------------
__global__ void scatter_kernel() {
    int n = blockIdx.x * blockDim.x + threadIdx.x;
    if (n >= Nn) return;
    int pk = g_tok_e[n];
    int e1 = pk & 255, e2 = (pk >> 8) & 255;
    int i1 = g_off[e1] + atomicAdd(&g_cursor[e1], 1);
    g_gtok[i1] = n; g_gp[i1] = g_tok_p1[n];
    int i2 = g_off[e2] + atomicAdd(&g_cursor[e2], 1);
    g_gtok[i2] = n; g_gp[i2] = g_tok_p2[n];
}

// ---------------- FFN mma.sync kernels (single-term fp16), double-buffered --------
// stage layout (bytes from stage base):
//   A [128][40]u16 @0       (10240 B)
//   B [32][136]u16 @10240   ( 8704 B)
// stage 18944 B, 2 stages = 37888 B dynamic smem
#define STG 18944
#define B_OF 10240
#define DYN_SMEM (2 * STG + 16)

template <int PASS>
__device__ __forceinline__ void load_stage(int tid, u32 st, int kofs,
                                           int e, int ncs, int row0, const int* s_tok) {
    constexpr int KD = (PASS == 1) ? Dd : Hh;
    constexpr int ND = (PASS == 1) ? Hh : Dd;
    const u16* Af = (PASS == 1) ? g_Xf : g_Hf;
    const u16* Bf = (PASS == 1) ? g_W1f : g_W2f;
#pragma unroll
    for (int i = 0; i < 2; i++) {           // A: 512 16B chunks
        int idx = tid + 256 * i;
        int row = idx >> 2, c = idx & 3;
        u32 d = st + row * 80 + c * 16;
        size_t g;
        if (PASS == 1) g = (size_t)s_tok[row] * Dd + kofs + c * 8;
        else           g = (size_t)(row0 + row) * Hh + kofs + c * 8;
        CP16(d, Af + g);
    }
#pragma unroll
    for (int i = 0; i < 2; i++) {           // B: 512 16B chunks
        int idx = tid + 256 * i;
        int row = idx >> 4, c = idx & 15;
        u32 d = st + B_OF + row * 272 + c * 16;
        size_t g = ((size_t)e * KD + kofs + row) * ND + ncs + c * 8;
        CP16(d, Bf + g);
    }
}

template <int PASS>
__global__ void __launch_bounds__(256, 1)
ffn_mma_kernel(const float* __restrict__ bias, float* __restrict__ dst) {
    constexpr int KD = (PASS == 1) ? Dd : Hh;
    constexpr int ND = (PASS == 1) ? Hh : Dd;
    constexpr int KS = KD / 32;

    extern __shared__ char dsm[];
    u32 base = (smem_u32(dsm) + 15) & ~15u;
    __shared__ int   s_tok[MT];
    __shared__ float s_p[MT];

    int b = blockIdx.x;
    if (b >= g_tileoff[Ee]) return;
    int e = 0;
#pragma unroll
    for (int i = 1; i < Ee; i++) if (b >= g_tileoff[i]) e = i;
    int tile  = b - g_tileoff[e];
    int row0  = g_off[e] + tile * MT;
    int nrows = min(MT, g_off[e + 1] - row0);
    int ncs   = blockIdx.y * 128;

    int tid = threadIdx.x;
    if (tid < MT) {
        if (tid < nrows) { s_tok[tid] = g_gtok[row0 + tid]; s_p[tid] = g_gp[row0 + tid]; }
        else             { s_tok[tid] = 0;                  s_p[tid] = 0.f; }
    }
    __syncthreads();

    int wid = tid >> 5, lane = tid & 31;
    int wm = wid >> 2, wn = wid & 3;
    int m0 = wm * 64, n0w = wn * 32;
    int lr = lane & 15, lc = (lane >> 4) << 3;

    float acc[4][4][4];
#pragma unroll
    for (int mi = 0; mi < 4; mi++)
#pragma unroll
        for (int ni = 0; ni < 4; ni++)
#pragma unroll
            for (int j = 0; j < 4; j++) acc[mi][ni][j] = 0.f;

    load_stage<PASS>(tid, base, 0, e, ncs, row0, s_tok);
    CPCOMMIT();

    for (int ks = 0; ks < KS; ks++) {
        u32 st = base + (u32)(ks & 1) * STG;
        if (ks + 1 < KS) {
            load_stage<PASS>(tid, base + (u32)((ks + 1) & 1) * STG,
                             (ks + 1) * 32, e, ncs, row0, s_tok);
            CPCOMMIT();
            cp_wait<1>();
        } else {
            cp_wait<0>();
        }
        __syncthreads();
#pragma unroll
        for (int k16 = 0; k16 < 2; k16++) {
            u32 a[4][4], bb[4][2];
#pragma unroll
            for (int mi = 0; mi < 4; mi++) {
                u32 arow = st + (u32)(m0 + mi * 16 + lr) * 80 + (u32)(k16 * 16 + lc) * 2;
                ldm4(arow, a[mi][0], a[mi][1], a[mi][2], a[mi][3]);
            }
#pragma unroll
            for (int nj = 0; nj < 2; nj++) {
                u32 brow = st + B_OF + (u32)(k16 * 16 + lr) * 272
                         + (u32)(n0w + nj * 16 + lc) * 2;
                ldm4t(brow, bb[2 * nj][0], bb[2 * nj][1], bb[2 * nj + 1][0], bb[2 * nj + 1][1]);
            }
#pragma unroll
            for (int mi = 0; mi < 4; mi++)
#pragma unroll
                for (int ni = 0; ni < 4; ni++)
                    mma16816(acc[mi][ni], a[mi][0], a[mi][1], a[mi][2], a[mi][3],
                             bb[ni][0], bb[ni][1]);
        }
        __syncthreads();
    }

    // ---- epilogue ----
    int gr = lane >> 2, gc = (lane & 3) * 2;
    const float* be = bias + (size_t)e * ND;
#pragma unroll
    for (int mi = 0; mi < 4; mi++) {
        int r1 = m0 + mi * 16 + gr;
        int r2 = r1 + 8;
#pragma unroll
        for (int ni = 0; ni < 4; ni++) {
            int col = ncs + n0w + ni * 8 + gc;
            float bv0 = be[col], bv1 = be[col + 1];
            if (PASS == 1) {
                if (r1 < nrows) {
                    float v0 = gelu_exact(acc[mi][ni][0] + bv0);
                    float v1 = gelu_exact(acc[mi][ni][1] + bv1);
                    *(u32*)&g_Hf[(size_t)(row0 + r1) * Hh + col] = pack_half2(v0, v1);
                }
                if (r2 < nrows) {
                    float v0 = gelu_exact(acc[mi][ni][2] + bv0);
                    float v1 = gelu_exact(acc[mi][ni][3] + bv1);
                    *(u32*)&g_Hf[(size_t)(row0 + r2) * Hh + col] = pack_half2(v0, v1);
                }
            } else {
                if (r1 < nrows) {
                    float p = s_p[r1];
                    float* orow = dst + (size_t)s_tok[r1] * Dd;
                    atomicAdd(orow + col,     (acc[mi][ni][0] + bv0) * p);
                    atomicAdd(orow + col + 1, (acc[mi][ni][1] + bv1) * p);
                }
                if (r2 < nrows) {
                    float p = s_p[r2];
                    float* orow = dst + (size_t)s_tok[r2] * Dd;
                    atomicAdd(orow + col,     (acc[mi][ni][2] + bv0) * p);
                    atomicAdd(orow + col + 1, (acc[mi][ni][3] + bv1) * p);
                }
            }
        }
    }
}

// ---------------- launcher ----------------
extern "C" void kernel_launch(void* const* d_in, const int* in_sizes, int n_in,
                              void* d_out, int out_size) {
    const float* x    = (const float*)d_in[0];
    const float* grad = (const float*)d_in[1];
    const float* Wr   = (const float*)d_in[2];
    const float* br   = (const float*)d_in[3];
    const float* W1   = (const float*)d_in[4];
    const float* b1   = (const float*)d_in[5];
    const float* W2   = (const float*)d_in[6];
    const float* b2   = (const float*)d_in[7];
    float* out   = (float*)d_out;
    float* probs = out + (size_t)Nn * Dd;

    cudaFuncSetAttribute(ffn_mma_kernel<1>,
                         cudaFuncAttributeMaxDynamicSharedMemorySize, DYN_SMEM);
    cudaFuncSetAttribute(ffn_mma_kernel<2>,
                         cudaFuncAttributeMaxDynamicSharedMemorySize, DYN_SMEM);

    zero_kernel<<<(Nn * Dd / 4 + 255) / 256, 256>>>((float4*)out);
    cvt_kernel<<<(XN4 + 2 * WN4) / 256, 256>>>((const float4*)x,
                                               (const float4*)W1, (const float4*)W2);
    router_kernel<<<Nn / 8, 256>>>(x, grad, Wr, br, probs);
    scan_kernel<<<1, 32>>>();
    scatter_kernel<<<Nn / 256, 256>>>();
    ffn_mma_kernel<1><<<dim3(TILES_MAX, Hh / 128), 256, DYN_SMEM>>>(b1, nullptr);
    ffn_mma_kernel<2><<<dim3(TILES_MAX, Dd / 128), 256, DYN_SMEM>>>(b2, out);
}

// round 10
// speedup vs baseline: 6.5548x; 1.3927x over previous
#include <cuda_runtime.h>
#include <cuda_fp16.h>
#include <math.h>

#define Nn 32768
#define Dd 256
#define Ee 8
#define Hh 1024
#define MT 128
#define TILES_MAX (Nn * 2 / MT + Ee)   // 520
#define HROWS (Nn * 2 + MT)            // 65664
#define XN4 (Nn * Dd / 4)              // 2097152
#define WN4 (Ee * Dd * Hh / 4)         // 524288

typedef unsigned short u16;
typedef unsigned int u32;
typedef unsigned long long u64;

// ---------------- device scratch (static, no allocation) ----------------
__device__ int   g_counts[Ee];
__device__ int   g_cursor[Ee];
__device__ int   g_off[Ee + 1];
__device__ int   g_tileoff[Ee + 1];
__device__ int   g_tok_e[Nn];
__device__ float g_tok_p1[Nn];
__device__ float g_tok_p2[Nn];
__device__ int   g_gtok[Nn * 2];
__device__ float g_gp[Nn * 2];

__device__ u16 g_Xf[Nn * Dd];                  // X as fp16 [n][k]
__device__ u16 g_W1f[Ee * Dd * Hh];            // W1 fp16 [e][k=256][n=1024]
__device__ u16 g_W2f[Ee * Dd * Hh];            // W2 fp16 [e][k=1024][n=256]
__device__ u16 g_Hf[(size_t)HROWS * Hh];       // hidden as fp16

// ---------------- helpers ----------------
__device__ __forceinline__ u32 smem_u32(const void* p) {
    return (u32)__cvta_generic_to_shared(p);
}
__device__ __forceinline__ u32 pack_half2(float a, float b) {
    __half ha = __float2half_rn(a), hb = __float2half_rn(b);
    return (u32)__half_as_ushort(ha) | ((u32)__half_as_ushort(hb) << 16);
}
__device__ __forceinline__ float gelu_exact(float v) {
    return 0.5f * v * (1.f + erff(v * 0.70710678118654752f));
}
#define CP16(dst, src) \
    asm volatile("cp.async.cg.shared.global [%0],[%1],16;" ::"r"(dst), "l"(src))
#define CPCOMMIT() asm volatile("cp.async.commit_group;" ::: "memory")
template <int N> __device__ __forceinline__ void cp_wait() {
    asm volatile("cp.async.wait_group %0;" ::"n"(N) : "memory");
}
__device__ __forceinline__ void ldm4(u32 addr, u32& r0, u32& r1, u32& r2, u32& r3) {
    asm volatile("ldmatrix.sync.aligned.m8n8.x4.shared.b16 {%0,%1,%2,%3},[%4];"
                 : "=r"(r0), "=r"(r1), "=r"(r2), "=r"(r3) : "r"(addr));
}
__device__ __forceinline__ void ldm4t(u32 addr, u32& r0, u32& r1, u32& r2, u32& r3) {
    asm volatile("ldmatrix.sync.aligned.m8n8.x4.trans.shared.b16 {%0,%1,%2,%3},[%4];"
                 : "=r"(r0), "=r"(r1), "=r"(r2), "=r"(r3) : "r"(addr));
}
__device__ __forceinline__ void mma16816(float* c, u32 a0, u32 a1, u32 a2, u32 a3,
                                         u32 b0, u32 b1) {
    asm volatile(
        "mma.sync.aligned.m16n8k16.row.col.f32.f16.f16.f32 "
        "{%0,%1,%2,%3},{%4,%5,%6,%7},{%8,%9},{%0,%1,%2,%3};"
        : "+f"(c[0]), "+f"(c[1]), "+f"(c[2]), "+f"(c[3])
        : "r"(a0), "r"(a1), "r"(a2), "r"(a3), "r"(b0), "r"(b1));
}

// ---------------- kernel 0: zero out + counters ----------------
__global__ void zero_kernel(float4* out4) {
    int i = blockIdx.x * blockDim.x + threadIdx.x;
    if (i < (Nn * Dd / 4)) out4[i] = make_float4(0.f, 0.f, 0.f, 0.f);
    if (blockIdx.x == 0 && threadIdx.x < Ee) {
        g_counts[threadIdx.x] = 0;
        g_cursor[threadIdx.x] = 0;
    }
}

// ---------------- kernel 1: convert X / W1 / W2 -> fp16 ----------------
__global__ void cvt_kernel(const float4* __restrict__ x4,
                           const float4* __restrict__ w14,
                           const float4* __restrict__ w24) {
    int i = blockIdx.x * 256 + threadIdx.x;
    float4 v;
    u16* dst;
    int j;
    if (i < XN4)                { v = x4[i];              dst = g_Xf;  j = i; }
    else if (i < XN4 + WN4)     { j = i - XN4;       v = w14[j]; dst = g_W1f; }
    else                        { j = i - XN4 - WN4; v = w24[j]; dst = g_W2f; }
    *(uint2*)&dst[(size_t)j * 4] =
        make_uint2(pack_half2(v.x, v.y), pack_half2(v.z, v.w));
}

// ---------------- kernel 2: router (fp32, exact selection) ----------------
__global__ void router_kernel(const float* __restrict__ x,
                              const float* __restrict__ grad,
                              const float* __restrict__ Wr,
                              const float* __restrict__ br,
                              float* __restrict__ probs_out) {
    __shared__ float WrT[Ee][Dd + 1];
    int tid = threadIdx.x;
    for (int i = tid; i < (Dd + 1) * Ee; i += blockDim.x) {
        int d = i >> 3, e = i & 7;
        WrT[e][d] = Wr[i];
    }
    __syncthreads();

    int wid = tid >> 5, lane = tid & 31;
    int n = blockIdx.x * 8 + wid;
    const float* xr = x + (size_t)n * Dd;

    float a[8];
#pragma unroll
    for (int e = 0; e < 8; e++) a[e] = 0.f;
#pragma unroll
    for (int j = 0; j < 8; j++) {
        float xv = xr[lane + 32 * j];
#pragma unroll
        for (int e = 0; e < 8; e++) a[e] += xv * WrT[e][lane + 32 * j];
    }
#pragma unroll
    for (int off = 16; off > 0; off >>= 1) {
#pragma unroll
        for (int e = 0; e < 8; e++) a[e] += __shfl_xor_sync(0xffffffffu, a[e], off);
    }

    if (lane == 0) {
        float g = grad[n];
        float p[8];
        float m = -1e30f;
#pragma unroll
        for (int e = 0; e < 8; e++) {
            p[e] = a[e] + g * WrT[e][Dd] + br[e];
            m = fmaxf(m, p[e]);
        }
        float s = 0.f;
#pragma unroll
        for (int e = 0; e < 8; e++) { p[e] = expf(p[e] - m); s += p[e]; }
        float inv = 1.f / s;
#pragma unroll
        for (int e = 0; e < 8; e++) {
            p[e] *= inv;
            probs_out[(size_t)n * 8 + e] = p[e];
        }
        int e1 = 0;
#pragma unroll
        for (int e = 1; e < 8; e++) if (p[e] > p[e1]) e1 = e;
        int e2 = (e1 == 0) ? 1 : 0;
#pragma unroll
        for (int e = 0; e < 8; e++) if (e != e1 && p[e] > p[e2]) e2 = e;

        g_tok_e[n]  = e1 | (e2 << 8);
        g_tok_p1[n] = p[e1];
        g_tok_p2[n] = p[e2];
        atomicAdd(&g_counts[e1], 1);
        atomicAdd(&g_counts[e2], 1);
    }
}

// ---------------- kernel 3: tiny scan ----------------
__global__ void scan_kernel() {
    if (threadIdx.x == 0) {
        int o = 0, t = 0;
#pragma unroll
        for (int e = 0; e < Ee; e++) {
            g_off[e] = o;
            g_tileoff[e] = t;
            o += g_counts[e];
            t += (g_counts[e] + MT - 1) / MT;
        }
        g_off[Ee] = o;
        g_tileoff[Ee] = t;
    }
}

// ---------------- kernel 4: scatter ----------------
__global__ void scatter_kernel() {
    int n = blockIdx.x * blockDim.x + threadIdx.x;
    if (n >= Nn) return;
    int pk = g_tok_e[n];
    int e1 = pk & 255, e2 = (pk >> 8) & 255;
    int i1 = g_off[e1] + atomicAdd(&g_cursor[e1], 1);
    g_gtok[i1] = n; g_gp[i1] = g_tok_p1[n];
    int i2 = g_off[e2] + atomicAdd(&g_cursor[e2], 1);
    g_gtok[i2] = n; g_gp[i2] = g_tok_p2[n];
}

// ---------------- FFN mma.sync kernels (fp16, BK=64, 2 CTA/SM) ----------------
// stage layout (bytes from stage base):
//   A [128][72]u16 @0       (18432 B)  row stride 144 B (16B bank-step, conflict-free)
//   B [64][136]u16 @18432   (17408 B)  row stride 272 B
// stage 35840 B, 2 stages = 71680 B dynamic smem  -> 2 CTAs/SM (143 KB < 227 KB)
#define BK 64
#define STG 35840
#define B_OF 18432
#define DYN_SMEM (2 * STG + 16)

template <int PASS>
__device__ __forceinline__ void load_stage(int tid, u32 st, int kofs,
                                           int e, int ncs, int row0, const int* s_tok) {
    constexpr int KD = (PASS == 1) ? Dd : Hh;
    constexpr int ND = (PASS == 1) ? Hh : Dd;
    const u16* Af = (PASS == 1) ? g_Xf : g_Hf;
    const u16* Bf = (PASS == 1) ? g_W1f : g_W2f;
#pragma unroll
    for (int i = 0; i < 4; i++) {           // A: 1024 16B chunks (128 rows x 8)
        int idx = tid + 256 * i;
        int row = idx >> 3, c = idx & 7;
        u32 d = st + row * 144 + c * 16;
        size_t g;
        if (PASS == 1) g = (size_t)s_tok[row] * Dd + kofs + c * 8;
        else           g = (size_t)(row0 + row) * Hh + kofs + c * 8;
        CP16(d, Af + g);
    }
#pragma unroll
    for (int i = 0; i < 4; i++) {           // B: 1024 16B chunks (64 rows x 16)
        int idx = tid + 256 * i;
        int row = idx >> 4, c = idx & 15;
        u32 d = st + B_OF + row * 272 + c * 16;
        size_t g = ((size_t)e * KD + kofs + row) * ND + ncs + c * 8;
        CP16(d, Bf + g);
    }
}

template <int PASS>
__global__ void __launch_bounds__(256, 2)
ffn_mma_kernel(const float* __restrict__ bias, float* __restrict__ dst) {
    constexpr int KD = (PASS == 1) ? Dd : Hh;
    constexpr int ND = (PASS == 1) ? Hh : Dd;
    constexpr int KS = KD / BK;

    extern __shared__ char dsm[];
    u32 base = (smem_u32(dsm) + 15) & ~15u;
    __shared__ int   s_tok[MT];
    __shared__ float s_p[MT];

    int b = blockIdx.x;
    if (b >= g_tileoff[Ee]) return;
    int e = 0;
#pragma unroll
    for (int i = 1; i < Ee; i++) if (b >= g_tileoff[i]) e = i;
    int tile  = b - g_tileoff[e];
    int row0  = g_off[e] + tile * MT;
    int nrows = min(MT, g_off[e + 1] - row0);
    int ncs   = blockIdx.y * 128;

    int tid = threadIdx.x;
    if (tid < MT) {
        if (tid < nrows) { s_tok[tid] = g_gtok[row0 + tid]; s_p[tid] = g_gp[row0 + tid]; }
        else             { s_tok[tid] = 0;                  s_p[tid] = 0.f; }
    }
    __syncthreads();

    int wid = tid >> 5, lane = tid & 31;
    int wm = wid >> 2, wn = wid & 3;
    int m0 = wm * 64, n0w = wn * 32;
    int lr = lane & 15, lc = (lane >> 4) << 3;

    float acc[4][4][4];
#pragma unroll
    for (int mi = 0; mi < 4; mi++)
#pragma unroll
        for (int ni = 0; ni < 4; ni++)
#pragma unroll
            for (int j = 0; j < 4; j++) acc[mi][ni][j] = 0.f;

    load_stage<PASS>(tid, base, 0, e, ncs, row0, s_tok);
    CPCOMMIT();

    for (int ks = 0; ks < KS; ks++) {
        u32 st = base + (u32)(ks & 1) * STG;
        if (ks + 1 < KS) {
            load_stage<PASS>(tid, base + (u32)((ks + 1) & 1) * STG,
                             (ks + 1) * BK, e, ncs, row0, s_tok);
            CPCOMMIT();
            cp_wait<1>();
        } else {
            cp_wait<0>();
        }
        __syncthreads();
#pragma unroll
        for (int k16 = 0; k16 < BK / 16; k16++) {
            u32 a[4][4], bb[4][2];
#pragma unroll
            for (int mi = 0; mi < 4; mi++) {
                u32 arow = st + (u32)(m0 + mi * 16 + lr) * 144 + (u32)(k16 * 16 + lc) * 2;
                ldm4(arow, a[mi][0], a[mi][1], a[mi][2], a[mi][3]);
            }
#pragma unroll
            for (int nj = 0; nj < 2; nj++) {
                u32 brow = st + B_OF + (u32)(k16 * 16 + lr) * 272
                         + (u32)(n0w + nj * 16 + lc) * 2;
                ldm4t(brow, bb[2 * nj][0], bb[2 * nj][1], bb[2 * nj + 1][0], bb[2 * nj + 1][1]);
            }
#pragma unroll
            for (int mi = 0; mi < 4; mi++)
#pragma unroll
                for (int ni = 0; ni < 4; ni++)
                    mma16816(acc[mi][ni], a[mi][0], a[mi][1], a[mi][2], a[mi][3],
                             bb[ni][0], bb[ni][1]);
        }
        __syncthreads();
    }

    // ---- epilogue ----
    int gr = lane >> 2, gc = (lane & 3) * 2;
    const float* be = bias + (size_t)e * ND;
#pragma unroll
    for (int mi = 0; mi < 4; mi++) {
        int r1 = m0 + mi * 16 + gr;
        int r2 = r1 + 8;
#pragma unroll
        for (int ni = 0; ni < 4; ni++) {
            int col = ncs + n0w + ni * 8 + gc;
            float bv0 = be[col], bv1 = be[col + 1];
            if (PASS == 1) {
                if (r1 < nrows) {
                    float v0 = gelu_exact(acc[mi][ni][0] + bv0);
                    float v1 = gelu_exact(acc[mi][ni][1] + bv1);
                    *(u32*)&g_Hf[(size_t)(row0 + r1) * Hh + col] = pack_half2(v0, v1);
                }
                if (r2 < nrows) {
                    float v0 = gelu_exact(acc[mi][ni][2] + bv0);
                    float v1 = gelu_exact(acc[mi][ni][3] + bv1);
                    *(u32*)&g_Hf[(size_t)(row0 + r2) * Hh + col] = pack_half2(v0, v1);
                }
            } else {
                if (r1 < nrows) {
                    float p = s_p[r1];
                    float* orow = dst + (size_t)s_tok[r1] * Dd;
                    atomicAdd(orow + col,     (acc[mi][ni][0] + bv0) * p);
                    atomicAdd(orow + col + 1, (acc[mi][ni][1] + bv1) * p);
                }
                if (r2 < nrows) {
                    float p = s_p[r2];
                    float* orow = dst + (size_t)s_tok[r2] * Dd;
                    atomicAdd(orow + col,     (acc[mi][ni][2] + bv0) * p);
                    atomicAdd(orow + col + 1, (acc[mi][ni][3] + bv1) * p);
                }
            }
        }
    }
}

// ---------------- launcher ----------------
extern "C" void kernel_launch(void* const* d_in, const int* in_sizes, int n_in,
                              void* d_out, int out_size) {
    const float* x    = (const float*)d_in[0];
    const float* grad = (const float*)d_in[1];
    const float* Wr   = (const float*)d_in[2];
    const float* br   = (const float*)d_in[3];
    const float* W1   = (const float*)d_in[4];
    const float* b1   = (const float*)d_in[5];
    const float* W2   = (const float*)d_in[6];
    const float* b2   = (const float*)d_in[7];
    float* out   = (float*)d_out;
    float* probs = out + (size_t)Nn * Dd;

    cudaFuncSetAttribute(ffn_mma_kernel<1>,
                         cudaFuncAttributeMaxDynamicSharedMemorySize, DYN_SMEM);
    cudaFuncSetAttribute(ffn_mma_kernel<2>,
                         cudaFuncAttributeMaxDynamicSharedMemorySize, DYN_SMEM);

    zero_kernel<<<(Nn * Dd / 4 + 255) / 256, 256>>>((float4*)out);
    cvt_kernel<<<(XN4 + 2 * WN4) / 256, 256>>>((const float4*)x,
                                               (const float4*)W1, (const float4*)W2);
    router_kernel<<<Nn / 8, 256>>>(x, grad, Wr, br, probs);
    scan_kernel<<<1, 32>>>();
    scatter_kernel<<<Nn / 256, 256>>>();
    ffn_mma_kernel<1><<<dim3(TILES_MAX, Hh / 128), 256, DYN_SMEM>>>(b1, nullptr);
    ffn_mma_kernel<2><<<dim3(TILES_MAX, Dd / 128), 256, DYN_SMEM>>>(b2, out);
}